// round 10
// baseline (speedup 1.0000x reference)
#include <cuda_runtime.h>
#include <cuda_bf16.h>
#include <math.h>

#define BB 8
#define LL 1024
#define DD 512
#define HH 8
#define DKK 64

// Scratch (__device__ globals; no runtime allocation)
__device__ float g_Q[BB*HH*LL*DKK];   // (B,H,L,DK) fp32
__device__ float g_K[BB*HH*LL*DKK];
__device__ float g_V[BB*HH*LL*DKK];
__device__ float g_X[BB*LL*DD];       // attention output (B,L,D) fp32

// m16n8k16 bf16 MMA. A row-major (16x16), B col-major (16x8), C fp32.
__device__ __forceinline__ void mma16(float* c, const unsigned* a, unsigned b0, unsigned b1) {
    asm volatile(
        "mma.sync.aligned.m16n8k16.row.col.f32.bf16.bf16.f32 "
        "{%0,%1,%2,%3}, {%4,%5,%6,%7}, {%8,%9}, {%0,%1,%2,%3};\n"
        : "+f"(c[0]), "+f"(c[1]), "+f"(c[2]), "+f"(c[3])
        : "r"(a[0]), "r"(a[1]), "r"(a[2]), "r"(a[3]), "r"(b0), "r"(b1));
}

__device__ __forceinline__ unsigned packbf(float lo_val, float hi_val) {
    unsigned d;
    asm("cvt.rn.bf16x2.f32 %0, %1, %2;" : "=r"(d) : "f"(hi_val), "f"(lo_val));
    return d;
}
__device__ __forceinline__ void splitbf2(float xe, float xo, unsigned& h, unsigned& l) {
    h = packbf(xe, xo);
    float fe = __uint_as_float(h << 16);
    float fo = __uint_as_float(h & 0xffff0000u);
    l = packbf(xe - fe, xo - fo);
}

__device__ __forceinline__ float ex2f(float x) {
    float r;
    asm("ex2.approx.f32 %0, %1;" : "=f"(r) : "f"(x));
    return r;
}

__device__ __forceinline__ void cpa16(unsigned dst, const void* src) {
    asm volatile("cp.async.ca.shared.global [%0], [%1], 16;\n" :: "r"(dst), "l"(src));
}
__device__ __forceinline__ void cpa_commit() {
    asm volatile("cp.async.commit_group;\n");
}
template <int N>
__device__ __forceinline__ void cpa_wait() {
    asm volatile("cp.async.wait_group %0;\n" :: "n"(N));
}

// ---------------------------------------------------------------------------
// 3xBF16 GEMM (R6-proven, unchanged): C[m,n] = sum_k A[m,k]*W[n,k] + bias[n]
// ---------------------------------------------------------------------------
#define GP 20

__global__ __launch_bounds__(256) void gemm_bf16(
    const float* __restrict__ A, const float* __restrict__ W,
    const float* __restrict__ bias, float* __restrict__ C, int headmode)
{
    __shared__ unsigned Ah[128*GP], Al[128*GP], Bh[64*GP], Bl[64*GP];

    const int tid  = threadIdx.x;
    const int lane = tid & 31;
    const int warp = tid >> 5;
    const int g = lane >> 2, t = lane & 3;
    const int wm = warp & 3, wn = warp >> 2;
    const int m0 = blockIdx.y << 7, n0 = blockIdx.x << 6;

    float c[2][4][4];
    #pragma unroll
    for (int mt = 0; mt < 2; mt++)
        #pragma unroll
        for (int nt = 0; nt < 4; nt++)
            #pragma unroll
            for (int k = 0; k < 4; k++) c[mt][nt][k] = 0.f;

    const float* Abase = A + (size_t)m0 * DD;
    const float* Wbase = W + (size_t)n0 * DD;

    float4 ra[4], rb[2];
    #pragma unroll
    for (int i = 0; i < 4; i++) {
        int idx = tid + (i << 8);
        ra[i] = *(const float4*)(Abase + (size_t)(idx >> 3) * DD + ((idx & 7) << 2));
    }
    #pragma unroll
    for (int i = 0; i < 2; i++) {
        int idx = tid + (i << 8);
        rb[i] = *(const float4*)(Wbase + (size_t)(idx >> 3) * DD + ((idx & 7) << 2));
    }

    for (int k0 = 0; k0 < DD; k0 += 32) {
        __syncthreads();
        #pragma unroll
        for (int i = 0; i < 4; i++) {
            int idx = tid + (i << 8);
            int row = idx >> 3, kp = (idx & 7) << 1;
            unsigned h0, l0, h1, l1;
            splitbf2(ra[i].x, ra[i].y, h0, l0);
            splitbf2(ra[i].z, ra[i].w, h1, l1);
            *(uint2*)&Ah[row*GP + kp] = make_uint2(h0, h1);
            *(uint2*)&Al[row*GP + kp] = make_uint2(l0, l1);
        }
        #pragma unroll
        for (int i = 0; i < 2; i++) {
            int idx = tid + (i << 8);
            int row = idx >> 3, kp = (idx & 7) << 1;
            unsigned h0, l0, h1, l1;
            splitbf2(rb[i].x, rb[i].y, h0, l0);
            splitbf2(rb[i].z, rb[i].w, h1, l1);
            *(uint2*)&Bh[row*GP + kp] = make_uint2(h0, h1);
            *(uint2*)&Bl[row*GP + kp] = make_uint2(l0, l1);
        }
        __syncthreads();

        if (k0 + 32 < DD) {
            #pragma unroll
            for (int i = 0; i < 4; i++) {
                int idx = tid + (i << 8);
                ra[i] = *(const float4*)(Abase + (size_t)(idx >> 3) * DD + k0 + 32 + ((idx & 7) << 2));
            }
            #pragma unroll
            for (int i = 0; i < 2; i++) {
                int idx = tid + (i << 8);
                rb[i] = *(const float4*)(Wbase + (size_t)(idx >> 3) * DD + k0 + 32 + ((idx & 7) << 2));
            }
        }

        #pragma unroll
        for (int kt = 0; kt < 2; kt++) {
            unsigned ah[2][4], al[2][4];
            #pragma unroll
            for (int mt = 0; mt < 2; mt++) {
                int r = wm * 32 + mt * 16 + g;
                ah[mt][0] = Ah[ r      *GP + kt*8 + t    ];
                ah[mt][1] = Ah[(r + 8) *GP + kt*8 + t    ];
                ah[mt][2] = Ah[ r      *GP + kt*8 + t + 4];
                ah[mt][3] = Ah[(r + 8) *GP + kt*8 + t + 4];
                al[mt][0] = Al[ r      *GP + kt*8 + t    ];
                al[mt][1] = Al[(r + 8) *GP + kt*8 + t    ];
                al[mt][2] = Al[ r      *GP + kt*8 + t + 4];
                al[mt][3] = Al[(r + 8) *GP + kt*8 + t + 4];
            }
            #pragma unroll
            for (int nt = 0; nt < 4; nt++) {
                int r = wn * 32 + nt * 8 + g;
                unsigned bh0 = Bh[r*GP + kt*8 + t    ];
                unsigned bh1 = Bh[r*GP + kt*8 + t + 4];
                unsigned bl0 = Bl[r*GP + kt*8 + t    ];
                unsigned bl1 = Bl[r*GP + kt*8 + t + 4];
                #pragma unroll
                for (int mt = 0; mt < 2; mt++) {
                    mma16(c[mt][nt], al[mt], bh0, bh1);
                    mma16(c[mt][nt], ah[mt], bl0, bl1);
                    mma16(c[mt][nt], ah[mt], bh0, bh1);
                }
            }
        }
    }

    #pragma unroll
    for (int nt = 0; nt < 4; nt++) {
        int n = n0 + wn * 32 + nt * 8 + 2 * t;
        float b0 = bias[n], b1 = bias[n + 1];
        #pragma unroll
        for (int mt = 0; mt < 2; mt++) {
            int m = m0 + wm * 32 + mt * 16 + g;
            if (headmode) {
                int b_ = m >> 10, l = m & 1023;
                int h = n >> 6, dk = n & 63;
                float* p0 = C + (((size_t)b_ * HH + h) * LL + l) * DKK + dk;
                float* p1 = C + (((size_t)b_ * HH + h) * LL + (l + 8)) * DKK + dk;
                *(float2*)p0 = make_float2(c[mt][nt][0] + b0, c[mt][nt][1] + b1);
                *(float2*)p1 = make_float2(c[mt][nt][2] + b0, c[mt][nt][3] + b1);
            } else {
                float* p0 = C + (size_t)m * DD + n;
                float* p1 = C + (size_t)(m + 8) * DD + n;
                *(float2*)p0 = make_float2(c[mt][nt][0] + b0, c[mt][nt][1] + b1);
                *(float2*)p1 = make_float2(c[mt][nt][2] + b0, c[mt][nt][3] + b1);
            }
        }
    }
}

// ---------------------------------------------------------------------------
// Flash attention: cp.async raw tile (single buffer) + cooperative convert
// into pre-split Kh/Kl/Vh/Vl (R6-proven layouts), in-register P, base-2
// softmax, hoisted dist/mask. Block = (bh, 64 q-rows), 128 thr (4 warps).
// smem: raw K[64][72] + raw V[64][68] = 35,840 B; split 9216 words = 36,864 B.
// Total 72,704 B -> 3 blocks/SM.
// Pipeline per tile: wait -> sync -> convert(raw->split) -> sync ->
//   cp.async(next tile -> raw) -> MMA/softmax from split buffers.
// ---------------------------------------------------------------------------
#define KRP 72
#define VRP 68
#define KP 36
#define VP 72
#define RAWW (64*KRP + 64*VRP)                    // 8960 floats
#define SPLITW (2*64*KP + 2*32*VP)                // 9216 words
#define SMEM_ATTN ((RAWW + SPLITW) * (int)sizeof(float))
#define LOG2E 1.4426950408889634f

__global__ __launch_bounds__(128, 3) void attn_bf16(
    const float* __restrict__ dist, const unsigned char* __restrict__ mask,
    const float* __restrict__ logwb)
{
    extern __shared__ float smf[];
    float* Kraw = smf;                       // [64][KRP]
    float* Vraw = smf + 64*KRP;              // [64][VRP]
    unsigned* Kh = (unsigned*)(smf + RAWW);  // [64][KP]
    unsigned* Kl = Kh + 64*KP;
    unsigned* Vh = Kl + 64*KP;               // [32][VP]
    unsigned* Vl = Vh + 32*VP;

    const int tid  = threadIdx.x;
    const int lane = tid & 31;
    const int warp = tid >> 5;
    const int g = lane >> 2, t = lane & 3;

    const int bh = blockIdx.y;
    const int b  = bh >> 3, h = bh & 7;
    const int q0 = blockIdx.x << 6;

    const float wb = __expf(logwb[h]) * LOG2E;   // base-2 folded bias weight

    const float* Kg = g_K + (size_t)bh * LL * DKK;
    const float* Vg = g_V + (size_t)bh * LL * DKK;
    const float* db = dist + (size_t)b * LL * LL;
    const unsigned char* mb = mask + (size_t)b * LL * LL;

    const unsigned kraw_u = (unsigned)__cvta_generic_to_shared(Kraw);
    const unsigned vraw_u = (unsigned)__cvta_generic_to_shared(Vraw);

    // --- prefetch tile 0 into raw ---
    for (int i = tid; i < 1024; i += 128) {
        int r = i >> 4, c4 = (i & 15) << 2;
        cpa16(kraw_u + (r*KRP + c4)*4, Kg + (size_t)r * DKK + c4);
        cpa16(vraw_u + (r*VRP + c4)*4, Vg + (size_t)r * DKK + c4);
    }
    cpa_commit();

    // --- Q fragments straight from gmem (scaled by 0.125*log2e) ---
    unsigned qh[4][4], ql[4][4];
    {
        const float qscale = 0.125f * LOG2E;
        const float* Qp  = g_Q + ((size_t)bh * LL + q0 + warp*16 + g) * DKK;
        const float* Qp8 = Qp + 8 * DKK;
        #pragma unroll
        for (int kt = 0; kt < 4; kt++) {
            int cb = kt*16 + 2*t;
            float2 f;
            f = *(const float2*)(Qp  + cb);     splitbf2(f.x*qscale, f.y*qscale, qh[kt][0], ql[kt][0]);
            f = *(const float2*)(Qp8 + cb);     splitbf2(f.x*qscale, f.y*qscale, qh[kt][1], ql[kt][1]);
            f = *(const float2*)(Qp  + cb + 8); splitbf2(f.x*qscale, f.y*qscale, qh[kt][2], ql[kt][2]);
            f = *(const float2*)(Qp8 + cb + 8); splitbf2(f.x*qscale, f.y*qscale, qh[kt][3], ql[kt][3]);
        }
    }

    float o[8][4];
    #pragma unroll
    for (int nt = 0; nt < 8; nt++)
        #pragma unroll
        for (int k = 0; k < 4; k++) o[nt][k] = 0.f;
    float mrow[2] = {-1e30f, -1e30f};
    float lrow[2] = {0.f, 0.f};

    const int qr0 = q0 + warp * 16 + g;

    for (int it = 0; it < 16; it++) {
        const int k0 = it << 6;

        cpa_wait<0>();
        __syncthreads();   // raw ready; split buffers from prev tile fully consumed

        // --- convert raw -> split (each element split ONCE, shared work) ---
        // K: [64 n][32 kpair] hi/lo
        for (int i = tid; i < 1024; i += 128) {
            int r = i >> 4, c4 = (i & 15) << 2;
            float4 kv = *(const float4*)(Kraw + r*KRP + c4);
            unsigned h0, l0, h1, l1;
            splitbf2(kv.x, kv.y, h0, l0);
            splitbf2(kv.z, kv.w, h1, l1);
            *(uint2*)&Kh[r*KP + (c4 >> 1)] = make_uint2(h0, h1);
            *(uint2*)&Kl[r*KP + (c4 >> 1)] = make_uint2(l0, l1);
        }
        // V: [32 kpair][64 n] hi/lo
        for (int i = tid; i < 512; i += 128) {
            int kp = i >> 4, c4 = (i & 15) << 2;
            float4 v0 = *(const float4*)(Vraw + (2*kp    )*VRP + c4);
            float4 v1 = *(const float4*)(Vraw + (2*kp + 1)*VRP + c4);
            unsigned h0,l0,h1,l1,h2,l2,h3,l3;
            splitbf2(v0.x, v1.x, h0, l0);
            splitbf2(v0.y, v1.y, h1, l1);
            splitbf2(v0.z, v1.z, h2, l2);
            splitbf2(v0.w, v1.w, h3, l3);
            *(uint4*)&Vh[kp*VP + c4] = make_uint4(h0, h1, h2, h3);
            *(uint4*)&Vl[kp*VP + c4] = make_uint4(l0, l1, l2, l3);
        }
        __syncthreads();   // split ready; raw now free

        // --- prefetch next tile into raw (overlaps MMA below) ---
        if (it + 1 < 16) {
            const float* Kn = Kg + (size_t)(k0 + 64) * DKK;
            const float* Vn = Vg + (size_t)(k0 + 64) * DKK;
            for (int i = tid; i < 1024; i += 128) {
                int r = i >> 4, c4 = (i & 15) << 2;
                cpa16(kraw_u + (r*KRP + c4)*4, Kn + (size_t)r * DKK + c4);
                cpa16(vraw_u + (r*VRP + c4)*4, Vn + (size_t)r * DKK + c4);
            }
            cpa_commit();
        }

        // hoisted dist/mask loads (in flight during S-MMA loop)
        float2 d0a[8], d1a[8];
        unsigned short mk0a[8], mk1a[8];
        #pragma unroll
        for (int nt = 0; nt < 8; nt++) {
            int col = k0 + nt*8 + 2*t;
            d0a[nt] = *(const float2*)(db + (size_t)qr0 * LL + col);
            d1a[nt] = *(const float2*)(db + (size_t)(qr0 + 8) * LL + col);
            mk0a[nt] = *(const unsigned short*)(mb + (size_t)qr0 * LL + col);
            mk1a[nt] = *(const unsigned short*)(mb + (size_t)(qr0 + 8) * LL + col);
        }

        // S = Q @ K^T (3xBF16, pre-split frags)
        float s[8][4];
        #pragma unroll
        for (int nt = 0; nt < 8; nt++)
            #pragma unroll
            for (int k = 0; k < 4; k++) s[nt][k] = 0.f;

        #pragma unroll
        for (int kt = 0; kt < 4; kt++) {
            #pragma unroll
            for (int nt = 0; nt < 8; nt++) {
                int br = (nt*8 + g) * KP + kt*8;
                unsigned bh0 = Kh[br + t], bh1 = Kh[br + t + 4];
                unsigned bl0 = Kl[br + t], bl1 = Kl[br + t + 4];
                mma16(s[nt], ql[kt], bh0, bh1);
                mma16(s[nt], qh[kt], bl0, bl1);
                mma16(s[nt], qh[kt], bh0, bh1);
            }
        }

        // distance bias + mask (base-2 domain)
        #pragma unroll
        for (int nt = 0; nt < 8; nt++) {
            s[nt][0] -= d0a[nt].x * wb; if (mk0a[nt] & 0xffu) s[nt][0] = -1e9f;
            s[nt][1] -= d0a[nt].y * wb; if (mk0a[nt] >> 8)    s[nt][1] = -1e9f;
            s[nt][2] -= d1a[nt].x * wb; if (mk1a[nt] & 0xffu) s[nt][2] = -1e9f;
            s[nt][3] -= d1a[nt].y * wb; if (mk1a[nt] >> 8)    s[nt][3] = -1e9f;
        }

        // online softmax (base 2)
        #pragma unroll
        for (int i = 0; i < 2; i++) {
            float mx = -1e30f;
            #pragma unroll
            for (int nt = 0; nt < 8; nt++)
                mx = fmaxf(mx, fmaxf(s[nt][2*i], s[nt][2*i + 1]));
            mx = fmaxf(mx, __shfl_xor_sync(0xffffffffu, mx, 1));
            mx = fmaxf(mx, __shfl_xor_sync(0xffffffffu, mx, 2));
            float mnew  = fmaxf(mrow[i], mx);
            float alpha = ex2f(mrow[i] - mnew);
            float sum = 0.f;
            #pragma unroll
            for (int nt = 0; nt < 8; nt++) {
                s[nt][2*i]     = ex2f(s[nt][2*i]     - mnew);
                s[nt][2*i + 1] = ex2f(s[nt][2*i + 1] - mnew);
                sum += s[nt][2*i] + s[nt][2*i + 1];
            }
            sum += __shfl_xor_sync(0xffffffffu, sum, 1);
            sum += __shfl_xor_sync(0xffffffffu, sum, 2);
            lrow[i] = lrow[i] * alpha + sum;
            mrow[i] = mnew;
            #pragma unroll
            for (int nt = 0; nt < 8; nt++) {
                o[nt][2*i]     *= alpha;
                o[nt][2*i + 1] *= alpha;
            }
        }

        // O += P @ V (3xBF16); P A-frags via in-lane permutation (validated)
        #pragma unroll
        for (int kt = 0; kt < 4; kt++) {
            unsigned pah[4], pal[4];
            splitbf2(s[2*kt  ][0], s[2*kt  ][1], pah[0], pal[0]);
            splitbf2(s[2*kt  ][2], s[2*kt  ][3], pah[1], pal[1]);
            splitbf2(s[2*kt+1][0], s[2*kt+1][1], pah[2], pal[2]);
            splitbf2(s[2*kt+1][2], s[2*kt+1][3], pah[3], pal[3]);
            #pragma unroll
            for (int nt = 0; nt < 8; nt++) {
                unsigned vh0 = Vh[(kt*8 + t    ) * VP + nt*8 + g];
                unsigned vh1 = Vh[(kt*8 + t + 4) * VP + nt*8 + g];
                unsigned vl0 = Vl[(kt*8 + t    ) * VP + nt*8 + g];
                unsigned vl1 = Vl[(kt*8 + t + 4) * VP + nt*8 + g];
                mma16(o[nt], pah, vl0, vl1);
                mma16(o[nt], pal, vh0, vh1);
                mma16(o[nt], pah, vh0, vh1);
            }
        }
    }

    // normalize + write X (B,L,D)
    float inv0 = 1.0f / lrow[0], inv1 = 1.0f / lrow[1];
    float* X0 = g_X + ((size_t)b * LL + qr0)     * DD + h * DKK;
    float* X1 = g_X + ((size_t)b * LL + qr0 + 8) * DD + h * DKK;
    #pragma unroll
    for (int nt = 0; nt < 8; nt++) {
        *(float2*)&X0[nt*8 + 2*t] = make_float2(o[nt][0] * inv0, o[nt][1] * inv0);
        *(float2*)&X1[nt*8 + 2*t] = make_float2(o[nt][2] * inv1, o[nt][3] * inv1);
    }
}

// ---------------------------------------------------------------------------
extern "C" void kernel_launch(void* const* d_in, const int* in_sizes, int n_in,
                              void* d_out, int out_size)
{
    const float* query = (const float*)d_in[0];
    const float* key   = (const float*)d_in[1];
    const float* value = (const float*)d_in[2];
    const float* dist  = (const float*)d_in[3];
    const unsigned char* mask = (const unsigned char*)d_in[4];
    const float* Wq = (const float*)d_in[5];
    const float* bq = (const float*)d_in[6];
    const float* Wk = (const float*)d_in[7];
    const float* bk = (const float*)d_in[8];
    const float* Wv = (const float*)d_in[9];
    const float* bv = (const float*)d_in[10];
    const float* Wo = (const float*)d_in[11];
    const float* bo = (const float*)d_in[12];
    const float* logwb = (const float*)d_in[13];

    void *pQ, *pK, *pV, *pX;
    cudaGetSymbolAddress(&pQ, g_Q);
    cudaGetSymbolAddress(&pK, g_K);
    cudaGetSymbolAddress(&pV, g_V);
    cudaGetSymbolAddress(&pX, g_X);

    cudaFuncSetAttribute(attn_bf16,
                         cudaFuncAttributeMaxDynamicSharedMemorySize, SMEM_ATTN);

    dim3 gg(DD / 64, (BB * LL) / 128);   // (8, 64)
    gemm_bf16<<<gg, 256>>>(query, Wq, bq, (float*)pQ, 1);
    gemm_bf16<<<gg, 256>>>(key,   Wk, bk, (float*)pK, 1);
    gemm_bf16<<<gg, 256>>>(value, Wv, bv, (float*)pV, 1);

    attn_bf16<<<dim3(LL / 64, BB * HH), 128, SMEM_ATTN>>>(dist, mask, logwb);

    gemm_bf16<<<gg, 256>>>((const float*)pX, Wo, bo, (float*)d_out, 0);
}

// round 13
// speedup vs baseline: 1.0709x; 1.0709x over previous
#include <cuda_runtime.h>
#include <cuda_bf16.h>
#include <cstdint>
#include <math.h>

#define BB 8
#define LL 1024
#define DD 512
#define HH 8
#define DKK 64
#define LOG2E 1.4426950408889634f
#define QSC (0.125f * LOG2E)

// Scratch (__device__ globals; no runtime allocation)
__device__ float    g_V[BB*HH*LL*DKK];       // V fp32 (B,H,L,DK) — vprep input
__device__ float    g_X[BB*LL*DD];           // attention output (B,L,D)
__device__ unsigned g_Qs [BB*HH*LL*64];      // Q pre-scaled split: [bh][l][32 hi | 32 lo] kpair words
__device__ unsigned g_Khl[BB*HH*LL*64];      // K split: same layout
__device__ unsigned g_Vhl[BB*HH*2*64*512];   // V split transposed: [bh][plane hi/lo][dk][512 kpair]

// ---------------------------------------------------------------------------
// helpers
// ---------------------------------------------------------------------------
__device__ __forceinline__ void mma16(float* c, const unsigned* a, unsigned b0, unsigned b1) {
    asm volatile(
        "mma.sync.aligned.m16n8k16.row.col.f32.bf16.bf16.f32 "
        "{%0,%1,%2,%3}, {%4,%5,%6,%7}, {%8,%9}, {%0,%1,%2,%3};\n"
        : "+f"(c[0]), "+f"(c[1]), "+f"(c[2]), "+f"(c[3])
        : "r"(a[0]), "r"(a[1]), "r"(a[2]), "r"(a[3]), "r"(b0), "r"(b1));
}
__device__ __forceinline__ unsigned packbf(float lo_val, float hi_val) {
    unsigned d;
    asm("cvt.rn.bf16x2.f32 %0, %1, %2;" : "=r"(d) : "f"(hi_val), "f"(lo_val));
    return d;
}
__device__ __forceinline__ void splitbf2(float xe, float xo, unsigned& h, unsigned& l) {
    h = packbf(xe, xo);
    float fe = __uint_as_float(h << 16);
    float fo = __uint_as_float(h & 0xffff0000u);
    l = packbf(xe - fe, xo - fo);
}
__device__ __forceinline__ float ex2f(float x) {
    float r;
    asm("ex2.approx.f32 %0, %1;" : "=f"(r) : "f"(x));
    return r;
}
__device__ __forceinline__ void cpa16(unsigned dst, const void* src) {
    asm volatile("cp.async.ca.shared.global [%0], [%1], 16;\n" :: "r"(dst), "l"(src));
}
__device__ __forceinline__ void cpa_commit() {
    asm volatile("cp.async.commit_group;\n");
}
template <int N>
__device__ __forceinline__ void cpa_wait() {
    asm volatile("cp.async.wait_group %0;\n" :: "n"(N));
}
__device__ __forceinline__ unsigned smem_addr32(const void* p) {
    unsigned a;
    asm("{ .reg .u64 tmp; cvta.to.shared.u64 tmp, %1; cvt.u32.u64 %0, tmp; }"
        : "=r"(a) : "l"(p));
    return a;
}

// ---------------------------------------------------------------------------
// 3xBF16 GEMM (R6-proven core): C[m,n] = sum_k A[m,k]*W[n,k] + bias[n]
// headmode: 0 = plain row-major C (output proj)
//           1 = (B,H,L,DK) fp32 scatter (V)
//           2 = K: split hi/lo -> g_Khl [bh][l][32 hi|32 lo]
//           3 = Q: scale by QSC then split -> g_Qs (same layout)
// ---------------------------------------------------------------------------
#define GP 20

__global__ __launch_bounds__(256) void gemm_bf16(
    const float* __restrict__ A, const float* __restrict__ W,
    const float* __restrict__ bias, float* __restrict__ C, int headmode)
{
    __shared__ unsigned Ah[128*GP], Al[128*GP], Bh[64*GP], Bl[64*GP];

    const int tid  = threadIdx.x;
    const int lane = tid & 31;
    const int warp = tid >> 5;
    const int g = lane >> 2, t = lane & 3;
    const int wm = warp & 3, wn = warp >> 2;
    const int m0 = blockIdx.y << 7, n0 = blockIdx.x << 6;

    float c[2][4][4];
    #pragma unroll
    for (int mt = 0; mt < 2; mt++)
        #pragma unroll
        for (int nt = 0; nt < 4; nt++)
            #pragma unroll
            for (int k = 0; k < 4; k++) c[mt][nt][k] = 0.f;

    const float* Abase = A + (size_t)m0 * DD;
    const float* Wbase = W + (size_t)n0 * DD;

    float4 ra[4], rb[2];
    #pragma unroll
    for (int i = 0; i < 4; i++) {
        int idx = tid + (i << 8);
        ra[i] = *(const float4*)(Abase + (size_t)(idx >> 3) * DD + ((idx & 7) << 2));
    }
    #pragma unroll
    for (int i = 0; i < 2; i++) {
        int idx = tid + (i << 8);
        rb[i] = *(const float4*)(Wbase + (size_t)(idx >> 3) * DD + ((idx & 7) << 2));
    }

    for (int k0 = 0; k0 < DD; k0 += 32) {
        __syncthreads();
        #pragma unroll
        for (int i = 0; i < 4; i++) {
            int idx = tid + (i << 8);
            int row = idx >> 3, kp = (idx & 7) << 1;
            unsigned h0, l0, h1, l1;
            splitbf2(ra[i].x, ra[i].y, h0, l0);
            splitbf2(ra[i].z, ra[i].w, h1, l1);
            *(uint2*)&Ah[row*GP + kp] = make_uint2(h0, h1);
            *(uint2*)&Al[row*GP + kp] = make_uint2(l0, l1);
        }
        #pragma unroll
        for (int i = 0; i < 2; i++) {
            int idx = tid + (i << 8);
            int row = idx >> 3, kp = (idx & 7) << 1;
            unsigned h0, l0, h1, l1;
            splitbf2(rb[i].x, rb[i].y, h0, l0);
            splitbf2(rb[i].z, rb[i].w, h1, l1);
            *(uint2*)&Bh[row*GP + kp] = make_uint2(h0, h1);
            *(uint2*)&Bl[row*GP + kp] = make_uint2(l0, l1);
        }
        __syncthreads();

        if (k0 + 32 < DD) {
            #pragma unroll
            for (int i = 0; i < 4; i++) {
                int idx = tid + (i << 8);
                ra[i] = *(const float4*)(Abase + (size_t)(idx >> 3) * DD + k0 + 32 + ((idx & 7) << 2));
            }
            #pragma unroll
            for (int i = 0; i < 2; i++) {
                int idx = tid + (i << 8);
                rb[i] = *(const float4*)(Wbase + (size_t)(idx >> 3) * DD + k0 + 32 + ((idx & 7) << 2));
            }
        }

        #pragma unroll
        for (int kt = 0; kt < 2; kt++) {
            unsigned ah[2][4], al[2][4];
            #pragma unroll
            for (int mt = 0; mt < 2; mt++) {
                int r = wm * 32 + mt * 16 + g;
                ah[mt][0] = Ah[ r      *GP + kt*8 + t    ];
                ah[mt][1] = Ah[(r + 8) *GP + kt*8 + t    ];
                ah[mt][2] = Ah[ r      *GP + kt*8 + t + 4];
                ah[mt][3] = Ah[(r + 8) *GP + kt*8 + t + 4];
                al[mt][0] = Al[ r      *GP + kt*8 + t    ];
                al[mt][1] = Al[(r + 8) *GP + kt*8 + t    ];
                al[mt][2] = Al[ r      *GP + kt*8 + t + 4];
                al[mt][3] = Al[(r + 8) *GP + kt*8 + t + 4];
            }
            #pragma unroll
            for (int nt = 0; nt < 4; nt++) {
                int r = wn * 32 + nt * 8 + g;
                unsigned bh0 = Bh[r*GP + kt*8 + t    ];
                unsigned bh1 = Bh[r*GP + kt*8 + t + 4];
                unsigned bl0 = Bl[r*GP + kt*8 + t    ];
                unsigned bl1 = Bl[r*GP + kt*8 + t + 4];
                #pragma unroll
                for (int mt = 0; mt < 2; mt++) {
                    mma16(c[mt][nt], al[mt], bh0, bh1);
                    mma16(c[mt][nt], ah[mt], bl0, bl1);
                    mma16(c[mt][nt], ah[mt], bh0, bh1);
                }
            }
        }
    }

    // epilogue
    #pragma unroll
    for (int nt = 0; nt < 4; nt++) {
        int n = n0 + wn * 32 + nt * 8 + 2 * t;
        float b0 = bias[n], b1 = bias[n + 1];
        #pragma unroll
        for (int mt = 0; mt < 2; mt++) {
            int m = m0 + wm * 32 + mt * 16 + g;
            float x0 = c[mt][nt][0] + b0, x1 = c[mt][nt][1] + b1;
            float x2 = c[mt][nt][2] + b0, x3 = c[mt][nt][3] + b1;
            if (headmode == 0) {
                *(float2*)(C + (size_t)m * DD + n)       = make_float2(x0, x1);
                *(float2*)(C + (size_t)(m + 8) * DD + n) = make_float2(x2, x3);
            } else {
                int b_ = m >> 10, l = m & 1023, hh = n >> 6;
                int dk = n & 63;
                size_t bhl = ((size_t)b_ * HH + hh) * LL + l;
                if (headmode == 1) {
                    float* p0 = C + bhl * DKK + dk;
                    *(float2*)p0             = make_float2(x0, x1);
                    *(float2*)(p0 + 8 * DKK) = make_float2(x2, x3);
                } else {
                    if (headmode == 3) { x0 *= QSC; x1 *= QSC; x2 *= QSC; x3 *= QSC; }
                    unsigned* dst = (headmode == 3 ? g_Qs : g_Khl) + bhl * 64 + (dk >> 1);
                    unsigned h0, l0, h1, l1;
                    splitbf2(x0, x1, h0, l0);
                    splitbf2(x2, x3, h1, l1);
                    dst[0]  = h0; dst[32] = l0;
                    dst[8*64] = h1; dst[8*64 + 32] = l1;
                }
            }
        }
    }
}

// ---------------------------------------------------------------------------
// V prep: transpose + split. g_V (B,H,L,DK) fp32 ->
// g_Vhl[bh][plane][dk][512 kpair], word (dk,kp) = packbf(V[2kp][dk], V[2kp+1][dk])
// grid (16 token-tiles, 64 bh), block 128: dk = tid&63, half = tid>>6.
// ---------------------------------------------------------------------------
__global__ __launch_bounds__(128) void vprep()
{
    const int bh = blockIdx.y;
    const int t0 = blockIdx.x << 6;           // 64 tokens
    const int tid = threadIdx.x;
    const int dk = tid & 63, kph = tid >> 6;  // 16 kpairs each

    const float* src = g_V + ((size_t)bh * LL + t0 + kph * 32) * DKK + dk;
    unsigned hi[16], lo[16];
    #pragma unroll
    for (int k = 0; k < 16; k++) {
        float v0 = src[(2*k    ) * DKK];
        float v1 = src[(2*k + 1) * DKK];
        splitbf2(v0, v1, hi[k], lo[k]);
    }
    unsigned* dh = g_Vhl + ((size_t)(bh*2    ) * 64 + dk) * 512 + (t0 >> 1) + kph * 16;
    unsigned* dl = g_Vhl + ((size_t)(bh*2 + 1) * 64 + dk) * 512 + (t0 >> 1) + kph * 16;
    #pragma unroll
    for (int k = 0; k < 16; k += 4) {
        *(uint4*)(dh + k) = make_uint4(hi[k], hi[k+1], hi[k+2], hi[k+3]);
        *(uint4*)(dl + k) = make_uint4(lo[k], lo[k+1], lo[k+2], lo[k+3]);
    }
}

// ---------------------------------------------------------------------------
// Flash attention: all operands pre-split in gmem; cp.async double-buffered
// K/V tiles in fragment-friendly conflict-free layouts; in-register P;
// base-2 softmax. Block = (bh, 64 q-rows), 128 thr (4 warps).
// smem tile: K [64 tok][68 w] + V [64 dk][68 w] (both: 32 hi | 32 lo cols),
// stride 68 words (272 B: 16B-aligned, bank pattern 4g+t all-distinct).
// Buffer = 34,816 B x2 = 69,632 B -> 3 blocks/SM.
// ---------------------------------------------------------------------------
#define ATS 68
#define BUFW (2 * 64 * ATS)                       // words per buffer (8704)
#define SMEM_ATTN (2 * BUFW * (int)sizeof(unsigned))

__global__ __launch_bounds__(128, 3) void attn_bf16(
    const float* __restrict__ dist, const unsigned char* __restrict__ mask,
    const float* __restrict__ logwb)
{
    extern __shared__ unsigned smw[];

    const int tid  = threadIdx.x;
    const int lane = tid & 31;
    const int warp = tid >> 5;
    const int g = lane >> 2, t = lane & 3;

    const int bh = blockIdx.y;
    const int b  = bh >> 3, h = bh & 7;
    const int q0 = blockIdx.x << 6;

    const float wb = __expf(logwb[h]) * LOG2E;

    const unsigned* Ksrc0 = g_Khl + (size_t)bh * LL * 64;
    const unsigned* Vh0 = g_Vhl + (size_t)(bh*2    ) * 64 * 512;
    const unsigned* Vl0 = g_Vhl + (size_t)(bh*2 + 1) * 64 * 512;
    const float* db = dist + (size_t)b * LL * LL;
    const unsigned char* mb = mask + (size_t)b * LL * LL;

    const unsigned smem_u = smem_addr32(smw);

    // prefetch tile k0 into buffer buf
    auto prefetch = [&](int buf, int k0) {
        unsigned kb = smem_u + buf * BUFW * 4;
        unsigned vb = kb + 64 * ATS * 4;
        const unsigned* Ks = Ksrc0 + (size_t)k0 * 64;
        for (int i = tid; i < 1024; i += 128) {        // K: 64 rows x 16 chunks
            int r = i >> 4, cc = i & 15;
            cpa16(kb + r * 272 + cc * 16, Ks + (size_t)r * 64 + cc * 4);
        }
        const unsigned* vh = Vh0 + (k0 >> 1);
        const unsigned* vl = Vl0 + (k0 >> 1);
        for (int i = tid; i < 512; i += 128) {         // V: 64 dk x 8 chunks x2
            int r = i >> 3, cc = i & 7;
            cpa16(vb + r * 272 +       cc * 16, vh + (size_t)r * 512 + cc * 4);
            cpa16(vb + r * 272 + 128 + cc * 16, vl + (size_t)r * 512 + cc * 4);
        }
    };

    prefetch(0, 0);
    cpa_commit();

    // Q fragments: pre-scaled, pre-split in gmem
    unsigned qh[4][4], ql[4][4];
    {
        const unsigned* Qp = g_Qs + ((size_t)bh * LL + q0 + warp*16 + g) * 64;
        #pragma unroll
        for (int kt = 0; kt < 4; kt++) {
            int w = kt*8 + t;
            qh[kt][0] = Qp[w];            ql[kt][0] = Qp[32 + w];
            qh[kt][1] = Qp[512 + w];      ql[kt][1] = Qp[512 + 32 + w];
            qh[kt][2] = Qp[w + 4];        ql[kt][2] = Qp[32 + w + 4];
            qh[kt][3] = Qp[512 + w + 4];  ql[kt][3] = Qp[512 + 32 + w + 4];
        }
    }

    float o[8][4];
    #pragma unroll
    for (int nt = 0; nt < 8; nt++)
        #pragma unroll
        for (int k = 0; k < 4; k++) o[nt][k] = 0.f;
    float mrow[2] = {-1e30f, -1e30f};
    float lrow[2] = {0.f, 0.f};

    const int qr0 = q0 + warp * 16 + g;

    for (int it = 0; it < 16; it++) {
        const int k0 = it << 6;
        unsigned* Ks = smw + (it & 1) * BUFW;
        unsigned* Vs = Ks + 64 * ATS;

        if (it + 1 < 16) {
            prefetch((it + 1) & 1, k0 + 64);
            cpa_commit();
            cpa_wait<1>();
        } else {
            cpa_wait<0>();
        }
        __syncthreads();

        // hoisted dist/mask loads (in flight during S-MMA loop)
        float2 d0a[8], d1a[8];
        unsigned short mk0a[8], mk1a[8];
        #pragma unroll
        for (int nt = 0; nt < 8; nt++) {
            int col = k0 + nt*8 + 2*t;
            d0a[nt] = *(const float2*)(db + (size_t)qr0 * LL + col);
            d1a[nt] = *(const float2*)(db + (size_t)(qr0 + 8) * LL + col);
            mk0a[nt] = *(const unsigned short*)(mb + (size_t)qr0 * LL + col);
            mk1a[nt] = *(const unsigned short*)(mb + (size_t)(qr0 + 8) * LL + col);
        }

        // S = Q @ K^T (3xBF16, zero conversions)
        float s[8][4];
        #pragma unroll
        for (int nt = 0; nt < 8; nt++)
            #pragma unroll
            for (int k = 0; k < 4; k++) s[nt][k] = 0.f;

        #pragma unroll
        for (int kt = 0; kt < 4; kt++) {
            #pragma unroll
            for (int nt = 0; nt < 8; nt++) {
                int br = (nt*8 + g) * ATS + kt*8 + t;
                unsigned bh0 = Ks[br],      bh1 = Ks[br + 4];
                unsigned bl0 = Ks[br + 32], bl1 = Ks[br + 36];
                mma16(s[nt], ql[kt], bh0, bh1);
                mma16(s[nt], qh[kt], bl0, bl1);
                mma16(s[nt], qh[kt], bh0, bh1);
            }
        }

        // distance bias + mask (base-2 domain)
        #pragma unroll
        for (int nt = 0; nt < 8; nt++) {
            s[nt][0] -= d0a[nt].x * wb; if (mk0a[nt] & 0xffu) s[nt][0] = -1e9f;
            s[nt][1] -= d0a[nt].y * wb; if (mk0a[nt] >> 8)    s[nt][1] = -1e9f;
            s[nt][2] -= d1a[nt].x * wb; if (mk1a[nt] & 0xffu) s[nt][2] = -1e9f;
            s[nt][3] -= d1a[nt].y * wb; if (mk1a[nt] >> 8)    s[nt][3] = -1e9f;
        }

        // online softmax (base 2)
        #pragma unroll
        for (int i = 0; i < 2; i++) {
            float mx = -1e30f;
            #pragma unroll
            for (int nt = 0; nt < 8; nt++)
                mx = fmaxf(mx, fmaxf(s[nt][2*i], s[nt][2*i + 1]));
            mx = fmaxf(mx, __shfl_xor_sync(0xffffffffu, mx, 1));
            mx = fmaxf(mx, __shfl_xor_sync(0xffffffffu, mx, 2));
            float mnew  = fmaxf(mrow[i], mx);
            float alpha = ex2f(mrow[i] - mnew);
            float sum = 0.f;
            #pragma unroll
            for (int nt = 0; nt < 8; nt++) {
                s[nt][2*i]     = ex2f(s[nt][2*i]     - mnew);
                s[nt][2*i + 1] = ex2f(s[nt][2*i + 1] - mnew);
                sum += s[nt][2*i] + s[nt][2*i + 1];
            }
            sum += __shfl_xor_sync(0xffffffffu, sum, 1);
            sum += __shfl_xor_sync(0xffffffffu, sum, 2);
            lrow[i] = lrow[i] * alpha + sum;
            mrow[i] = mnew;
            #pragma unroll
            for (int nt = 0; nt < 8; nt++) {
                o[nt][2*i]     *= alpha;
                o[nt][2*i + 1] *= alpha;
            }
        }

        // O += P @ V (3xBF16); P A-frags via in-lane permutation (validated)
        #pragma unroll
        for (int kt = 0; kt < 4; kt++) {
            unsigned pah[4], pal[4];
            splitbf2(s[2*kt  ][0], s[2*kt  ][1], pah[0], pal[0]);
            splitbf2(s[2*kt  ][2], s[2*kt  ][3], pah[1], pal[1]);
            splitbf2(s[2*kt+1][0], s[2*kt+1][1], pah[2], pal[2]);
            splitbf2(s[2*kt+1][2], s[2*kt+1][3], pah[3], pal[3]);
            #pragma unroll
            for (int nt = 0; nt < 8; nt++) {
                int vr = (nt*8 + g) * ATS + kt*8 + t;
                unsigned vh0 = Vs[vr],      vh1 = Vs[vr + 4];
                unsigned vl0 = Vs[vr + 32], vl1 = Vs[vr + 36];
                mma16(o[nt], pah, vl0, vl1);
                mma16(o[nt], pal, vh0, vh1);
                mma16(o[nt], pah, vh0, vh1);
            }
        }
        __syncthreads();
    }

    // normalize + write X (B,L,D)
    float inv0 = 1.0f / lrow[0], inv1 = 1.0f / lrow[1];
    float* X0 = g_X + ((size_t)b * LL + qr0)     * DD + h * DKK;
    float* X1 = g_X + ((size_t)b * LL + qr0 + 8) * DD + h * DKK;
    #pragma unroll
    for (int nt = 0; nt < 8; nt++) {
        *(float2*)&X0[nt*8 + 2*t] = make_float2(o[nt][0] * inv0, o[nt][1] * inv0);
        *(float2*)&X1[nt*8 + 2*t] = make_float2(o[nt][2] * inv1, o[nt][3] * inv1);
    }
}

// ---------------------------------------------------------------------------
extern "C" void kernel_launch(void* const* d_in, const int* in_sizes, int n_in,
                              void* d_out, int out_size)
{
    const float* query = (const float*)d_in[0];
    const float* key   = (const float*)d_in[1];
    const float* value = (const float*)d_in[2];
    const float* dist  = (const float*)d_in[3];
    const unsigned char* mask = (const unsigned char*)d_in[4];
    const float* Wq = (const float*)d_in[5];
    const float* bq = (const float*)d_in[6];
    const float* Wk = (const float*)d_in[7];
    const float* bk = (const float*)d_in[8];
    const float* Wv = (const float*)d_in[9];
    const float* bv = (const float*)d_in[10];
    const float* Wo = (const float*)d_in[11];
    const float* bo = (const float*)d_in[12];
    const float* logwb = (const float*)d_in[13];

    void *pV, *pX;
    cudaGetSymbolAddress(&pV, g_V);
    cudaGetSymbolAddress(&pX, g_X);

    cudaFuncSetAttribute(attn_bf16,
                         cudaFuncAttributeMaxDynamicSharedMemorySize, SMEM_ATTN);

    dim3 gg(DD / 64, (BB * LL) / 128);   // (8, 64)
    gemm_bf16<<<gg, 256>>>(query, Wq, bq, (float*)pX, 3);  // Q -> g_Qs (C unused)
    gemm_bf16<<<gg, 256>>>(key,   Wk, bk, (float*)pX, 2);  // K -> g_Khl (C unused)
    gemm_bf16<<<gg, 256>>>(value, Wv, bv, (float*)pV, 1);  // V -> g_V fp32

    vprep<<<dim3(LL / 64, BB * HH), 128>>>();              // g_V -> g_Vhl

    attn_bf16<<<dim3(LL / 64, BB * HH), 128, SMEM_ATTN>>>(dist, mask, logwb);

    gemm_bf16<<<gg, 256>>>((const float*)pX, Wo, bo, (float*)d_out, 0);
}

// round 14
// speedup vs baseline: 1.1186x; 1.0445x over previous
#include <cuda_runtime.h>
#include <cuda_bf16.h>
#include <cstdint>
#include <math.h>

#define BB 8
#define LL 1024
#define DD 512
#define HH 8
#define DKK 64
#define LOG2E 1.4426950408889634f
#define QSC (0.125f * LOG2E)

// Scratch (__device__ globals; no runtime allocation)
__device__ float    g_V[BB*HH*LL*DKK];       // V fp32 (B,H,L,DK) — vprep input
__device__ float    g_X[BB*LL*DD];           // attention output (B,L,D)
__device__ unsigned g_Qs [BB*HH*LL*64];      // Q pre-scaled split: [bh][l][32 hi | 32 lo]
__device__ unsigned g_Khl[BB*HH*LL*64];      // K split: same layout
__device__ unsigned g_Vhl[BB*HH*2*64*512];   // V split transposed: [bh][plane][dk][512 kpair]

// ---------------------------------------------------------------------------
// helpers
// ---------------------------------------------------------------------------
__device__ __forceinline__ void mma16(float* c, const unsigned* a, unsigned b0, unsigned b1) {
    asm volatile(
        "mma.sync.aligned.m16n8k16.row.col.f32.bf16.bf16.f32 "
        "{%0,%1,%2,%3}, {%4,%5,%6,%7}, {%8,%9}, {%0,%1,%2,%3};\n"
        : "+f"(c[0]), "+f"(c[1]), "+f"(c[2]), "+f"(c[3])
        : "r"(a[0]), "r"(a[1]), "r"(a[2]), "r"(a[3]), "r"(b0), "r"(b1));
}
__device__ __forceinline__ unsigned packbf(float lo_val, float hi_val) {
    unsigned d;
    asm("cvt.rn.bf16x2.f32 %0, %1, %2;" : "=r"(d) : "f"(hi_val), "f"(lo_val));
    return d;
}
__device__ __forceinline__ void splitbf2(float xe, float xo, unsigned& h, unsigned& l) {
    h = packbf(xe, xo);
    float fe = __uint_as_float(h << 16);
    float fo = __uint_as_float(h & 0xffff0000u);
    l = packbf(xe - fe, xo - fo);
}
__device__ __forceinline__ float ex2f(float x) {
    float r;
    asm("ex2.approx.f32 %0, %1;" : "=f"(r) : "f"(x));
    return r;
}
__device__ __forceinline__ void cpa16(unsigned dst, const void* src) {
    asm volatile("cp.async.ca.shared.global [%0], [%1], 16;\n" :: "r"(dst), "l"(src));
}
__device__ __forceinline__ void cpa_commit() {
    asm volatile("cp.async.commit_group;\n");
}
template <int N>
__device__ __forceinline__ void cpa_wait() {
    asm volatile("cp.async.wait_group %0;\n" :: "n"(N));
}
__device__ __forceinline__ unsigned smem_addr32(const void* p) {
    unsigned a;
    asm("{ .reg .u64 tmp; cvta.to.shared.u64 tmp, %1; cvt.u32.u64 %0, tmp; }"
        : "=r"(a) : "l"(p));
    return a;
}

// ---------------------------------------------------------------------------
// 3xBF16 GEMM core (R6-proven) as a template-free inline: computes the
// 128x64 C tile for (A, W) and leaves results + bias in c[][][].
// ---------------------------------------------------------------------------
#define GP 20

struct GemmCore {
    float c[2][4][4];
};

__device__ __forceinline__ void gemm_core_run(
    const float* __restrict__ A, const float* __restrict__ W,
    int m0, int n0, int tid,
    unsigned* Ah, unsigned* Al, unsigned* Bh, unsigned* Bl,
    GemmCore& gc)
{
    const int lane = tid & 31;
    const int warp = tid >> 5;
    const int g = lane >> 2, t = lane & 3;
    const int wm = warp & 3, wn = warp >> 2;

    #pragma unroll
    for (int mt = 0; mt < 2; mt++)
        #pragma unroll
        for (int nt = 0; nt < 4; nt++)
            #pragma unroll
            for (int k = 0; k < 4; k++) gc.c[mt][nt][k] = 0.f;

    const float* Abase = A + (size_t)m0 * DD;
    const float* Wbase = W + (size_t)n0 * DD;

    float4 ra[4], rb[2];
    #pragma unroll
    for (int i = 0; i < 4; i++) {
        int idx = tid + (i << 8);
        ra[i] = *(const float4*)(Abase + (size_t)(idx >> 3) * DD + ((idx & 7) << 2));
    }
    #pragma unroll
    for (int i = 0; i < 2; i++) {
        int idx = tid + (i << 8);
        rb[i] = *(const float4*)(Wbase + (size_t)(idx >> 3) * DD + ((idx & 7) << 2));
    }

    for (int k0 = 0; k0 < DD; k0 += 32) {
        __syncthreads();
        #pragma unroll
        for (int i = 0; i < 4; i++) {
            int idx = tid + (i << 8);
            int row = idx >> 3, kp = (idx & 7) << 1;
            unsigned h0, l0, h1, l1;
            splitbf2(ra[i].x, ra[i].y, h0, l0);
            splitbf2(ra[i].z, ra[i].w, h1, l1);
            *(uint2*)&Ah[row*GP + kp] = make_uint2(h0, h1);
            *(uint2*)&Al[row*GP + kp] = make_uint2(l0, l1);
        }
        #pragma unroll
        for (int i = 0; i < 2; i++) {
            int idx = tid + (i << 8);
            int row = idx >> 3, kp = (idx & 7) << 1;
            unsigned h0, l0, h1, l1;
            splitbf2(rb[i].x, rb[i].y, h0, l0);
            splitbf2(rb[i].z, rb[i].w, h1, l1);
            *(uint2*)&Bh[row*GP + kp] = make_uint2(h0, h1);
            *(uint2*)&Bl[row*GP + kp] = make_uint2(l0, l1);
        }
        __syncthreads();

        if (k0 + 32 < DD) {
            #pragma unroll
            for (int i = 0; i < 4; i++) {
                int idx = tid + (i << 8);
                ra[i] = *(const float4*)(Abase + (size_t)(idx >> 3) * DD + k0 + 32 + ((idx & 7) << 2));
            }
            #pragma unroll
            for (int i = 0; i < 2; i++) {
                int idx = tid + (i << 8);
                rb[i] = *(const float4*)(Wbase + (size_t)(idx >> 3) * DD + k0 + 32 + ((idx & 7) << 2));
            }
        }

        #pragma unroll
        for (int kt = 0; kt < 2; kt++) {
            unsigned ah[2][4], al[2][4];
            #pragma unroll
            for (int mt = 0; mt < 2; mt++) {
                int r = wm * 32 + mt * 16 + g;
                ah[mt][0] = Ah[ r      *GP + kt*8 + t    ];
                ah[mt][1] = Ah[(r + 8) *GP + kt*8 + t    ];
                ah[mt][2] = Ah[ r      *GP + kt*8 + t + 4];
                ah[mt][3] = Ah[(r + 8) *GP + kt*8 + t + 4];
                al[mt][0] = Al[ r      *GP + kt*8 + t    ];
                al[mt][1] = Al[(r + 8) *GP + kt*8 + t    ];
                al[mt][2] = Al[ r      *GP + kt*8 + t + 4];
                al[mt][3] = Al[(r + 8) *GP + kt*8 + t + 4];
            }
            #pragma unroll
            for (int nt = 0; nt < 4; nt++) {
                int r = wn * 32 + nt * 8 + g;
                unsigned bh0 = Bh[r*GP + kt*8 + t    ];
                unsigned bh1 = Bh[r*GP + kt*8 + t + 4];
                unsigned bl0 = Bl[r*GP + kt*8 + t    ];
                unsigned bl1 = Bl[r*GP + kt*8 + t + 4];
                #pragma unroll
                for (int mt = 0; mt < 2; mt++) {
                    mma16(gc.c[mt][nt], al[mt], bh0, bh1);
                    mma16(gc.c[mt][nt], ah[mt], bl0, bl1);
                    mma16(gc.c[mt][nt], ah[mt], bh0, bh1);
                }
            }
        }
    }
}

// ---------------------------------------------------------------------------
// Fused Q/K/V projection GEMM: z=0 -> Q (scaled split -> g_Qs),
// z=1 -> K (split -> g_Khl), z=2 -> V (fp32 -> g_V).
// ---------------------------------------------------------------------------
__global__ __launch_bounds__(256) void gemm_qkv(
    const float* __restrict__ Aq, const float* __restrict__ Wq, const float* __restrict__ bq,
    const float* __restrict__ Ak, const float* __restrict__ Wk, const float* __restrict__ bk,
    const float* __restrict__ Av, const float* __restrict__ Wv, const float* __restrict__ bv)
{
    __shared__ unsigned Ah[128*GP], Al[128*GP], Bh[64*GP], Bl[64*GP];

    const int z = blockIdx.z;
    const float* A = (z == 0) ? Aq : (z == 1) ? Ak : Av;
    const float* W = (z == 0) ? Wq : (z == 1) ? Wk : Wv;
    const float* bias = (z == 0) ? bq : (z == 1) ? bk : bv;

    const int tid = threadIdx.x;
    const int lane = tid & 31;
    const int warp = tid >> 5;
    const int g = lane >> 2, t = lane & 3;
    const int wm = warp & 3, wn = warp >> 2;
    const int m0 = blockIdx.y << 7, n0 = blockIdx.x << 6;

    GemmCore gc;
    gemm_core_run(A, W, m0, n0, tid, Ah, Al, Bh, Bl, gc);

    #pragma unroll
    for (int nt = 0; nt < 4; nt++) {
        int n = n0 + wn * 32 + nt * 8 + 2 * t;
        float b0 = bias[n], b1 = bias[n + 1];
        #pragma unroll
        for (int mt = 0; mt < 2; mt++) {
            int m = m0 + wm * 32 + mt * 16 + g;
            float x0 = gc.c[mt][nt][0] + b0, x1 = gc.c[mt][nt][1] + b1;
            float x2 = gc.c[mt][nt][2] + b0, x3 = gc.c[mt][nt][3] + b1;
            int b_ = m >> 10, l = m & 1023, hh = n >> 6;
            int dk = n & 63;
            size_t bhl = ((size_t)b_ * HH + hh) * LL + l;
            if (z == 2) {
                float* p0 = g_V + bhl * DKK + dk;
                *(float2*)p0             = make_float2(x0, x1);
                *(float2*)(p0 + 8 * DKK) = make_float2(x2, x3);
            } else {
                if (z == 0) { x0 *= QSC; x1 *= QSC; x2 *= QSC; x3 *= QSC; }
                unsigned* dst = (z == 0 ? g_Qs : g_Khl) + bhl * 64 + (dk >> 1);
                unsigned h0, l0, h1, l1;
                splitbf2(x0, x1, h0, l0);
                splitbf2(x2, x3, h1, l1);
                dst[0]  = h0; dst[32] = l0;
                dst[8*64] = h1; dst[8*64 + 32] = l1;
            }
        }
    }
}

// Output projection GEMM (plain row-major C)
__global__ __launch_bounds__(256) void gemm_out(
    const float* __restrict__ A, const float* __restrict__ W,
    const float* __restrict__ bias, float* __restrict__ C)
{
    __shared__ unsigned Ah[128*GP], Al[128*GP], Bh[64*GP], Bl[64*GP];

    const int tid = threadIdx.x;
    const int lane = tid & 31;
    const int warp = tid >> 5;
    const int g = lane >> 2, t = lane & 3;
    const int wm = warp & 3, wn = warp >> 2;
    const int m0 = blockIdx.y << 7, n0 = blockIdx.x << 6;

    GemmCore gc;
    gemm_core_run(A, W, m0, n0, tid, Ah, Al, Bh, Bl, gc);

    #pragma unroll
    for (int nt = 0; nt < 4; nt++) {
        int n = n0 + wn * 32 + nt * 8 + 2 * t;
        float b0 = bias[n], b1 = bias[n + 1];
        #pragma unroll
        for (int mt = 0; mt < 2; mt++) {
            int m = m0 + wm * 32 + mt * 16 + g;
            *(float2*)(C + (size_t)m * DD + n) =
                make_float2(gc.c[mt][nt][0] + b0, gc.c[mt][nt][1] + b1);
            *(float2*)(C + (size_t)(m + 8) * DD + n) =
                make_float2(gc.c[mt][nt][2] + b0, gc.c[mt][nt][3] + b1);
        }
    }
}

// ---------------------------------------------------------------------------
// V prep (unchanged R13): g_V (B,H,L,DK) fp32 -> g_Vhl split dk-major.
// ---------------------------------------------------------------------------
__global__ __launch_bounds__(128) void vprep()
{
    const int bh = blockIdx.y;
    const int t0 = blockIdx.x << 6;
    const int tid = threadIdx.x;
    const int dk = tid & 63, kph = tid >> 6;

    const float* src = g_V + ((size_t)bh * LL + t0 + kph * 32) * DKK + dk;
    unsigned hi[16], lo[16];
    #pragma unroll
    for (int k = 0; k < 16; k++) {
        float v0 = src[(2*k    ) * DKK];
        float v1 = src[(2*k + 1) * DKK];
        splitbf2(v0, v1, hi[k], lo[k]);
    }
    unsigned* dh = g_Vhl + ((size_t)(bh*2    ) * 64 + dk) * 512 + (t0 >> 1) + kph * 16;
    unsigned* dl = g_Vhl + ((size_t)(bh*2 + 1) * 64 + dk) * 512 + (t0 >> 1) + kph * 16;
    #pragma unroll
    for (int k = 0; k < 16; k += 4) {
        *(uint4*)(dh + k) = make_uint4(hi[k], hi[k+1], hi[k+2], hi[k+3]);
        *(uint4*)(dl + k) = make_uint4(lo[k], lo[k+1], lo[k+2], lo[k+3]);
    }
}

// ---------------------------------------------------------------------------
// Flash attention (R13 layouts, single-sync pipeline):
// per iter: wait tile -> ONE syncthreads -> issue prefetch(it+1) -> compute.
// Buffer (it+1)&1 was last read in iter it-1; the top sync of iter it proves
// all warps finished it -> overwrite is race-free with one sync per iter.
// ---------------------------------------------------------------------------
#define ATS 68
#define BUFW (2 * 64 * ATS)
#define SMEM_ATTN (2 * BUFW * (int)sizeof(unsigned))

__global__ __launch_bounds__(128, 3) void attn_bf16(
    const float* __restrict__ dist, const unsigned char* __restrict__ mask,
    const float* __restrict__ logwb)
{
    extern __shared__ unsigned smw[];

    const int tid  = threadIdx.x;
    const int lane = tid & 31;
    const int warp = tid >> 5;
    const int g = lane >> 2, t = lane & 3;

    const int bh = blockIdx.y;
    const int b  = bh >> 3, h = bh & 7;
    const int q0 = blockIdx.x << 6;

    const float wb = __expf(logwb[h]) * LOG2E;

    const unsigned* Ksrc0 = g_Khl + (size_t)bh * LL * 64;
    const unsigned* Vh0 = g_Vhl + (size_t)(bh*2    ) * 64 * 512;
    const unsigned* Vl0 = g_Vhl + (size_t)(bh*2 + 1) * 64 * 512;
    const float* db = dist + (size_t)b * LL * LL;
    const unsigned char* mb = mask + (size_t)b * LL * LL;

    const unsigned smem_u = smem_addr32(smw);

    auto prefetch = [&](int buf, int k0) {
        unsigned kb = smem_u + buf * BUFW * 4;
        unsigned vb = kb + 64 * ATS * 4;
        const unsigned* Ks = Ksrc0 + (size_t)k0 * 64;
        for (int i = tid; i < 1024; i += 128) {
            int r = i >> 4, cc = i & 15;
            cpa16(kb + r * 272 + cc * 16, Ks + (size_t)r * 64 + cc * 4);
        }
        const unsigned* vh = Vh0 + (k0 >> 1);
        const unsigned* vl = Vl0 + (k0 >> 1);
        for (int i = tid; i < 512; i += 128) {
            int r = i >> 3, cc = i & 7;
            cpa16(vb + r * 272 +       cc * 16, vh + (size_t)r * 512 + cc * 4);
            cpa16(vb + r * 272 + 128 + cc * 16, vl + (size_t)r * 512 + cc * 4);
        }
    };

    prefetch(0, 0);
    cpa_commit();

    // Q fragments: pre-scaled, pre-split in gmem
    unsigned qh[4][4], ql[4][4];
    {
        const unsigned* Qp = g_Qs + ((size_t)bh * LL + q0 + warp*16 + g) * 64;
        #pragma unroll
        for (int kt = 0; kt < 4; kt++) {
            int w = kt*8 + t;
            qh[kt][0] = Qp[w];            ql[kt][0] = Qp[32 + w];
            qh[kt][1] = Qp[512 + w];      ql[kt][1] = Qp[512 + 32 + w];
            qh[kt][2] = Qp[w + 4];        ql[kt][2] = Qp[32 + w + 4];
            qh[kt][3] = Qp[512 + w + 4];  ql[kt][3] = Qp[512 + 32 + w + 4];
        }
    }

    float o[8][4];
    #pragma unroll
    for (int nt = 0; nt < 8; nt++)
        #pragma unroll
        for (int k = 0; k < 4; k++) o[nt][k] = 0.f;
    float mrow[2] = {-1e30f, -1e30f};
    float lrow[2] = {0.f, 0.f};

    const int qr0 = q0 + warp * 16 + g;

    for (int it = 0; it < 16; it++) {
        const int k0 = it << 6;
        unsigned* Ks = smw + (it & 1) * BUFW;
        unsigned* Vs = Ks + 64 * ATS;

        cpa_wait<0>();       // current tile landed
        __syncthreads();     // everyone done with the OTHER buffer (iter it-1)

        if (it + 1 < 16) {
            prefetch((it + 1) & 1, k0 + 64);   // safe: other buffer now free
            cpa_commit();
        }

        // hoisted dist/mask loads (in flight during S-MMA loop)
        float2 d0a[8], d1a[8];
        unsigned short mk0a[8], mk1a[8];
        #pragma unroll
        for (int nt = 0; nt < 8; nt++) {
            int col = k0 + nt*8 + 2*t;
            d0a[nt] = *(const float2*)(db + (size_t)qr0 * LL + col);
            d1a[nt] = *(const float2*)(db + (size_t)(qr0 + 8) * LL + col);
            mk0a[nt] = *(const unsigned short*)(mb + (size_t)qr0 * LL + col);
            mk1a[nt] = *(const unsigned short*)(mb + (size_t)(qr0 + 8) * LL + col);
        }

        // S = Q @ K^T (3xBF16, zero conversions)
        float s[8][4];
        #pragma unroll
        for (int nt = 0; nt < 8; nt++)
            #pragma unroll
            for (int k = 0; k < 4; k++) s[nt][k] = 0.f;

        #pragma unroll
        for (int kt = 0; kt < 4; kt++) {
            #pragma unroll
            for (int nt = 0; nt < 8; nt++) {
                int br = (nt*8 + g) * ATS + kt*8 + t;
                unsigned bh0 = Ks[br],      bh1 = Ks[br + 4];
                unsigned bl0 = Ks[br + 32], bl1 = Ks[br + 36];
                mma16(s[nt], ql[kt], bh0, bh1);
                mma16(s[nt], qh[kt], bl0, bl1);
                mma16(s[nt], qh[kt], bh0, bh1);
            }
        }

        // distance bias + mask (base-2 domain)
        #pragma unroll
        for (int nt = 0; nt < 8; nt++) {
            s[nt][0] -= d0a[nt].x * wb; if (mk0a[nt] & 0xffu) s[nt][0] = -1e9f;
            s[nt][1] -= d0a[nt].y * wb; if (mk0a[nt] >> 8)    s[nt][1] = -1e9f;
            s[nt][2] -= d1a[nt].x * wb; if (mk1a[nt] & 0xffu) s[nt][2] = -1e9f;
            s[nt][3] -= d1a[nt].y * wb; if (mk1a[nt] >> 8)    s[nt][3] = -1e9f;
        }

        // online softmax (base 2)
        #pragma unroll
        for (int i = 0; i < 2; i++) {
            float mx = -1e30f;
            #pragma unroll
            for (int nt = 0; nt < 8; nt++)
                mx = fmaxf(mx, fmaxf(s[nt][2*i], s[nt][2*i + 1]));
            mx = fmaxf(mx, __shfl_xor_sync(0xffffffffu, mx, 1));
            mx = fmaxf(mx, __shfl_xor_sync(0xffffffffu, mx, 2));
            float mnew  = fmaxf(mrow[i], mx);
            float alpha = ex2f(mrow[i] - mnew);
            float sum = 0.f;
            #pragma unroll
            for (int nt = 0; nt < 8; nt++) {
                s[nt][2*i]     = ex2f(s[nt][2*i]     - mnew);
                s[nt][2*i + 1] = ex2f(s[nt][2*i + 1] - mnew);
                sum += s[nt][2*i] + s[nt][2*i + 1];
            }
            sum += __shfl_xor_sync(0xffffffffu, sum, 1);
            sum += __shfl_xor_sync(0xffffffffu, sum, 2);
            lrow[i] = lrow[i] * alpha + sum;
            mrow[i] = mnew;
            #pragma unroll
            for (int nt = 0; nt < 8; nt++) {
                o[nt][2*i]     *= alpha;
                o[nt][2*i + 1] *= alpha;
            }
        }

        // O += P @ V (3xBF16); P A-frags via in-lane permutation (validated)
        #pragma unroll
        for (int kt = 0; kt < 4; kt++) {
            unsigned pah[4], pal[4];
            splitbf2(s[2*kt  ][0], s[2*kt  ][1], pah[0], pal[0]);
            splitbf2(s[2*kt  ][2], s[2*kt  ][3], pah[1], pal[1]);
            splitbf2(s[2*kt+1][0], s[2*kt+1][1], pah[2], pal[2]);
            splitbf2(s[2*kt+1][2], s[2*kt+1][3], pah[3], pal[3]);
            #pragma unroll
            for (int nt = 0; nt < 8; nt++) {
                int vr = (nt*8 + g) * ATS + kt*8 + t;
                unsigned vh0 = Vs[vr],      vh1 = Vs[vr + 4];
                unsigned vl0 = Vs[vr + 32], vl1 = Vs[vr + 36];
                mma16(o[nt], pah, vl0, vl1);
                mma16(o[nt], pal, vh0, vh1);
                mma16(o[nt], pah, vh0, vh1);
            }
        }
    }

    // normalize + write X (B,L,D)
    float inv0 = 1.0f / lrow[0], inv1 = 1.0f / lrow[1];
    float* X0 = g_X + ((size_t)b * LL + qr0)     * DD + h * DKK;
    float* X1 = g_X + ((size_t)b * LL + qr0 + 8) * DD + h * DKK;
    #pragma unroll
    for (int nt = 0; nt < 8; nt++) {
        *(float2*)&X0[nt*8 + 2*t] = make_float2(o[nt][0] * inv0, o[nt][1] * inv0);
        *(float2*)&X1[nt*8 + 2*t] = make_float2(o[nt][2] * inv1, o[nt][3] * inv1);
    }
}

// ---------------------------------------------------------------------------
extern "C" void kernel_launch(void* const* d_in, const int* in_sizes, int n_in,
                              void* d_out, int out_size)
{
    const float* query = (const float*)d_in[0];
    const float* key   = (const float*)d_in[1];
    const float* value = (const float*)d_in[2];
    const float* dist  = (const float*)d_in[3];
    const unsigned char* mask = (const unsigned char*)d_in[4];
    const float* Wq = (const float*)d_in[5];
    const float* bq = (const float*)d_in[6];
    const float* Wk = (const float*)d_in[7];
    const float* bk = (const float*)d_in[8];
    const float* Wv = (const float*)d_in[9];
    const float* bv = (const float*)d_in[10];
    const float* Wo = (const float*)d_in[11];
    const float* bo = (const float*)d_in[12];
    const float* logwb = (const float*)d_in[13];

    void *pX;
    cudaGetSymbolAddress(&pX, g_X);

    cudaFuncSetAttribute(attn_bf16,
                         cudaFuncAttributeMaxDynamicSharedMemorySize, SMEM_ATTN);

    // fused Q/K/V projections: 1536 CTAs in one launch
    dim3 gqkv(DD / 64, (BB * LL) / 128, 3);
    gemm_qkv<<<gqkv, 256>>>(query, Wq, bq, key, Wk, bk, value, Wv, bv);

    vprep<<<dim3(LL / 64, BB * HH), 128>>>();

    attn_bf16<<<dim3(LL / 64, BB * HH), 128, SMEM_ATTN>>>(dist, mask, logwb);

    dim3 go(DD / 64, (BB * LL) / 128);
    gemm_out<<<go, 256>>>((const float*)pX, Wo, bo, (float*)d_out);
}

// round 15
// speedup vs baseline: 1.1730x; 1.0486x over previous
#include <cuda_runtime.h>
#include <cuda_bf16.h>
#include <cstdint>
#include <math.h>

#define BB 8
#define LL 1024
#define DD 512
#define HH 8
#define DKK 64
#define LOG2E 1.4426950408889634f
#define QSC (0.125f * LOG2E)

// Scratch (__device__ globals; no runtime allocation)
__device__ float    g_X[BB*LL*DD];           // attention output (B,L,D)
__device__ unsigned g_Qs [BB*HH*LL*64];      // Q pre-scaled split: [bh][l][32 hi | 32 lo] (bf16x2)
__device__ unsigned g_Khl[BB*HH*LL*64];      // K split: same layout (bf16x2)
__device__ unsigned g_Vhl[BB*HH*2*64*512];   // V fp16 split: [bh][plane hi/lo][dk][512 kpair] (f16x2)

// ---------------------------------------------------------------------------
// helpers
// ---------------------------------------------------------------------------
__device__ __forceinline__ void mma16(float* c, const unsigned* a, unsigned b0, unsigned b1) {
    asm volatile(
        "mma.sync.aligned.m16n8k16.row.col.f32.bf16.bf16.f32 "
        "{%0,%1,%2,%3}, {%4,%5,%6,%7}, {%8,%9}, {%0,%1,%2,%3};\n"
        : "+f"(c[0]), "+f"(c[1]), "+f"(c[2]), "+f"(c[3])
        : "r"(a[0]), "r"(a[1]), "r"(a[2]), "r"(a[3]), "r"(b0), "r"(b1));
}
__device__ __forceinline__ void mma16h(float* c, const unsigned* a, unsigned b0, unsigned b1) {
    asm volatile(
        "mma.sync.aligned.m16n8k16.row.col.f32.f16.f16.f32 "
        "{%0,%1,%2,%3}, {%4,%5,%6,%7}, {%8,%9}, {%0,%1,%2,%3};\n"
        : "+f"(c[0]), "+f"(c[1]), "+f"(c[2]), "+f"(c[3])
        : "r"(a[0]), "r"(a[1]), "r"(a[2]), "r"(a[3]), "r"(b0), "r"(b1));
}
__device__ __forceinline__ unsigned packbf(float lo_val, float hi_val) {
    unsigned d;
    asm("cvt.rn.bf16x2.f32 %0, %1, %2;" : "=r"(d) : "f"(hi_val), "f"(lo_val));
    return d;
}
__device__ __forceinline__ void splitbf2(float xe, float xo, unsigned& h, unsigned& l) {
    h = packbf(xe, xo);
    float fe = __uint_as_float(h << 16);
    float fo = __uint_as_float(h & 0xffff0000u);
    l = packbf(xe - fe, xo - fo);
}
__device__ __forceinline__ unsigned packf16(float lo_val, float hi_val) {
    unsigned d;
    asm("cvt.rn.f16x2.f32 %0, %1, %2;" : "=r"(d) : "f"(hi_val), "f"(lo_val));
    return d;
}
__device__ __forceinline__ void splitf162(float xe, float xo, unsigned& h, unsigned& l) {
    h = packf16(xe, xo);
    float fe, fo;
    asm("{ .reg .f16 a, b;\n\t"
        "mov.b32 {a, b}, %2;\n\t"
        "cvt.f32.f16 %0, a;\n\t"
        "cvt.f32.f16 %1, b; }"
        : "=f"(fe), "=f"(fo) : "r"(h));
    l = packf16(xe - fe, xo - fo);
}
__device__ __forceinline__ float ex2f(float x) {
    float r;
    asm("ex2.approx.f32 %0, %1;" : "=f"(r) : "f"(x));
    return r;
}
__device__ __forceinline__ void cpa16(unsigned dst, const void* src) {
    asm volatile("cp.async.ca.shared.global [%0], [%1], 16;\n" :: "r"(dst), "l"(src));
}
__device__ __forceinline__ void cpa_commit() {
    asm volatile("cp.async.commit_group;\n");
}
template <int N>
__device__ __forceinline__ void cpa_wait() {
    asm volatile("cp.async.wait_group %0;\n" :: "n"(N));
}
__device__ __forceinline__ unsigned smem_addr32(const void* p) {
    unsigned a;
    asm("{ .reg .u64 tmp; cvta.to.shared.u64 tmp, %1; cvt.u32.u64 %0, tmp; }"
        : "=r"(a) : "l"(p));
    return a;
}

// ---------------------------------------------------------------------------
// 3xBF16 GEMM core (R6-proven): 128x64 C tile, results left in gc.c
// ---------------------------------------------------------------------------
#define GP 20

struct GemmCore {
    float c[2][4][4];
};

__device__ __forceinline__ void gemm_core_run(
    const float* __restrict__ A, const float* __restrict__ W,
    int m0, int n0, int tid,
    unsigned* Ah, unsigned* Al, unsigned* Bh, unsigned* Bl,
    GemmCore& gc)
{
    const int lane = tid & 31;
    const int warp = tid >> 5;
    const int g = lane >> 2, t = lane & 3;
    const int wm = warp & 3, wn = warp >> 2;

    #pragma unroll
    for (int mt = 0; mt < 2; mt++)
        #pragma unroll
        for (int nt = 0; nt < 4; nt++)
            #pragma unroll
            for (int k = 0; k < 4; k++) gc.c[mt][nt][k] = 0.f;

    const float* Abase = A + (size_t)m0 * DD;
    const float* Wbase = W + (size_t)n0 * DD;

    float4 ra[4], rb[2];
    #pragma unroll
    for (int i = 0; i < 4; i++) {
        int idx = tid + (i << 8);
        ra[i] = *(const float4*)(Abase + (size_t)(idx >> 3) * DD + ((idx & 7) << 2));
    }
    #pragma unroll
    for (int i = 0; i < 2; i++) {
        int idx = tid + (i << 8);
        rb[i] = *(const float4*)(Wbase + (size_t)(idx >> 3) * DD + ((idx & 7) << 2));
    }

    for (int k0 = 0; k0 < DD; k0 += 32) {
        __syncthreads();
        #pragma unroll
        for (int i = 0; i < 4; i++) {
            int idx = tid + (i << 8);
            int row = idx >> 3, kp = (idx & 7) << 1;
            unsigned h0, l0, h1, l1;
            splitbf2(ra[i].x, ra[i].y, h0, l0);
            splitbf2(ra[i].z, ra[i].w, h1, l1);
            *(uint2*)&Ah[row*GP + kp] = make_uint2(h0, h1);
            *(uint2*)&Al[row*GP + kp] = make_uint2(l0, l1);
        }
        #pragma unroll
        for (int i = 0; i < 2; i++) {
            int idx = tid + (i << 8);
            int row = idx >> 3, kp = (idx & 7) << 1;
            unsigned h0, l0, h1, l1;
            splitbf2(rb[i].x, rb[i].y, h0, l0);
            splitbf2(rb[i].z, rb[i].w, h1, l1);
            *(uint2*)&Bh[row*GP + kp] = make_uint2(h0, h1);
            *(uint2*)&Bl[row*GP + kp] = make_uint2(l0, l1);
        }
        __syncthreads();

        if (k0 + 32 < DD) {
            #pragma unroll
            for (int i = 0; i < 4; i++) {
                int idx = tid + (i << 8);
                ra[i] = *(const float4*)(Abase + (size_t)(idx >> 3) * DD + k0 + 32 + ((idx & 7) << 2));
            }
            #pragma unroll
            for (int i = 0; i < 2; i++) {
                int idx = tid + (i << 8);
                rb[i] = *(const float4*)(Wbase + (size_t)(idx >> 3) * DD + k0 + 32 + ((idx & 7) << 2));
            }
        }

        #pragma unroll
        for (int kt = 0; kt < 2; kt++) {
            unsigned ah[2][4], al[2][4];
            #pragma unroll
            for (int mt = 0; mt < 2; mt++) {
                int r = wm * 32 + mt * 16 + g;
                ah[mt][0] = Ah[ r      *GP + kt*8 + t    ];
                ah[mt][1] = Ah[(r + 8) *GP + kt*8 + t    ];
                ah[mt][2] = Ah[ r      *GP + kt*8 + t + 4];
                ah[mt][3] = Ah[(r + 8) *GP + kt*8 + t + 4];
                al[mt][0] = Al[ r      *GP + kt*8 + t    ];
                al[mt][1] = Al[(r + 8) *GP + kt*8 + t    ];
                al[mt][2] = Al[ r      *GP + kt*8 + t + 4];
                al[mt][3] = Al[(r + 8) *GP + kt*8 + t + 4];
            }
            #pragma unroll
            for (int nt = 0; nt < 4; nt++) {
                int r = wn * 32 + nt * 8 + g;
                unsigned bh0 = Bh[r*GP + kt*8 + t    ];
                unsigned bh1 = Bh[r*GP + kt*8 + t + 4];
                unsigned bl0 = Bl[r*GP + kt*8 + t    ];
                unsigned bl1 = Bl[r*GP + kt*8 + t + 4];
                #pragma unroll
                for (int mt = 0; mt < 2; mt++) {
                    mma16(gc.c[mt][nt], al[mt], bh0, bh1);
                    mma16(gc.c[mt][nt], ah[mt], bl0, bl1);
                    mma16(gc.c[mt][nt], ah[mt], bh0, bh1);
                }
            }
        }
    }
}

// ---------------------------------------------------------------------------
// Fused Q/K/V projection GEMM: z=0 -> Q (scaled bf16 split -> g_Qs),
// z=1 -> K (bf16 split -> g_Khl),
// z=2 -> V (fp16 split + token-pair transpose -> g_Vhl, vprep folded in).
// ---------------------------------------------------------------------------
__global__ __launch_bounds__(256) void gemm_qkv(
    const float* __restrict__ Aq, const float* __restrict__ Wq, const float* __restrict__ bq,
    const float* __restrict__ Ak, const float* __restrict__ Wk, const float* __restrict__ bk,
    const float* __restrict__ Av, const float* __restrict__ Wv, const float* __restrict__ bv)
{
    __shared__ unsigned Ah[128*GP], Al[128*GP], Bh[64*GP], Bl[64*GP];

    const int z = blockIdx.z;
    const float* A = (z == 0) ? Aq : (z == 1) ? Ak : Av;
    const float* W = (z == 0) ? Wq : (z == 1) ? Wk : Wv;
    const float* bias = (z == 0) ? bq : (z == 1) ? bk : bv;

    const int tid = threadIdx.x;
    const int lane = tid & 31;
    const int warp = tid >> 5;
    const int g = lane >> 2, t = lane & 3;
    const int wm = warp & 3, wn = warp >> 2;
    const int m0 = blockIdx.y << 7, n0 = blockIdx.x << 6;

    GemmCore gc;
    gemm_core_run(A, W, m0, n0, tid, Ah, Al, Bh, Bl, gc);

    #pragma unroll
    for (int nt = 0; nt < 4; nt++) {
        int n = n0 + wn * 32 + nt * 8 + 2 * t;
        float b0 = bias[n], b1 = bias[n + 1];
        #pragma unroll
        for (int mt = 0; mt < 2; mt++) {
            int m = m0 + wm * 32 + mt * 16 + g;
            float x0 = gc.c[mt][nt][0] + b0, x1 = gc.c[mt][nt][1] + b1;
            float x2 = gc.c[mt][nt][2] + b0, x3 = gc.c[mt][nt][3] + b1;
            int b_ = m >> 10, l = m & 1023, hh = n >> 6;
            int dk = n & 63;
            if (z == 2) {
                // V: folded transpose+split via partner exchange (g <-> g^1)
                float y0 = __shfl_xor_sync(0xffffffffu, x0, 4);
                float y1 = __shfl_xor_sync(0xffffffffu, x1, 4);
                float y2 = __shfl_xor_sync(0xffffffffu, x2, 4);
                float y3 = __shfl_xor_sync(0xffffffffu, x3, 4);
                int bhh = b_ * HH + hh;
                unsigned* vh = g_Vhl + (size_t)(bhh * 2    ) * 64 * 512;
                unsigned* vl = g_Vhl + (size_t)(bhh * 2 + 1) * 64 * 512;
                unsigned h, lw;
                if ((g & 1) == 0) {
                    // token pair (m, m+1), rows of l: kp = (l)>>1 (l even here)
                    int kp = l >> 1;
                    splitf162(x0, y0, h, lw);
                    vh[(size_t)dk * 512 + kp] = h;  vl[(size_t)dk * 512 + kp] = lw;
                    splitf162(x1, y1, h, lw);
                    vh[(size_t)(dk+1) * 512 + kp] = h;  vl[(size_t)(dk+1) * 512 + kp] = lw;
                } else {
                    // token pair (l+7, l+8): even token from partner (y2/y3)
                    int kp = (l + 7) >> 1;
                    splitf162(y2, x2, h, lw);
                    vh[(size_t)dk * 512 + kp] = h;  vl[(size_t)dk * 512 + kp] = lw;
                    splitf162(y3, x3, h, lw);
                    vh[(size_t)(dk+1) * 512 + kp] = h;  vl[(size_t)(dk+1) * 512 + kp] = lw;
                }
            } else {
                if (z == 0) { x0 *= QSC; x1 *= QSC; x2 *= QSC; x3 *= QSC; }
                size_t bhl = ((size_t)b_ * HH + hh) * LL + l;
                unsigned* dst = (z == 0 ? g_Qs : g_Khl) + bhl * 64 + (dk >> 1);
                unsigned h0, l0, h1, l1;
                splitbf2(x0, x1, h0, l0);
                splitbf2(x2, x3, h1, l1);
                dst[0]  = h0; dst[32] = l0;
                dst[8*64] = h1; dst[8*64 + 32] = l1;
            }
        }
    }
}

// ---------------------------------------------------------------------------
// Output projection GEMM: 2xFP16 (A rounded to fp16, W split hi/lo).
// Error ~2.8e-4 rms relative (A-residual dropped) — safe vs 1e-3 gate.
// ---------------------------------------------------------------------------
__global__ __launch_bounds__(256) void gemm_out(
    const float* __restrict__ A, const float* __restrict__ W,
    const float* __restrict__ bias, float* __restrict__ C)
{
    __shared__ unsigned Fh[128*GP], Bh[64*GP], Bl[64*GP];

    const int tid = threadIdx.x;
    const int lane = tid & 31;
    const int warp = tid >> 5;
    const int g = lane >> 2, t = lane & 3;
    const int wm = warp & 3, wn = warp >> 2;
    const int m0 = blockIdx.y << 7, n0 = blockIdx.x << 6;

    float c[2][4][4];
    #pragma unroll
    for (int mt = 0; mt < 2; mt++)
        #pragma unroll
        for (int nt = 0; nt < 4; nt++)
            #pragma unroll
            for (int k = 0; k < 4; k++) c[mt][nt][k] = 0.f;

    const float* Abase = A + (size_t)m0 * DD;
    const float* Wbase = W + (size_t)n0 * DD;

    float4 ra[4], rb[2];
    #pragma unroll
    for (int i = 0; i < 4; i++) {
        int idx = tid + (i << 8);
        ra[i] = *(const float4*)(Abase + (size_t)(idx >> 3) * DD + ((idx & 7) << 2));
    }
    #pragma unroll
    for (int i = 0; i < 2; i++) {
        int idx = tid + (i << 8);
        rb[i] = *(const float4*)(Wbase + (size_t)(idx >> 3) * DD + ((idx & 7) << 2));
    }

    for (int k0 = 0; k0 < DD; k0 += 32) {
        __syncthreads();
        #pragma unroll
        for (int i = 0; i < 4; i++) {
            int idx = tid + (i << 8);
            int row = idx >> 3, kp = (idx & 7) << 1;
            *(uint2*)&Fh[row*GP + kp] =
                make_uint2(packf16(ra[i].x, ra[i].y), packf16(ra[i].z, ra[i].w));
        }
        #pragma unroll
        for (int i = 0; i < 2; i++) {
            int idx = tid + (i << 8);
            int row = idx >> 3, kp = (idx & 7) << 1;
            unsigned h0, l0, h1, l1;
            splitf162(rb[i].x, rb[i].y, h0, l0);
            splitf162(rb[i].z, rb[i].w, h1, l1);
            *(uint2*)&Bh[row*GP + kp] = make_uint2(h0, h1);
            *(uint2*)&Bl[row*GP + kp] = make_uint2(l0, l1);
        }
        __syncthreads();

        if (k0 + 32 < DD) {
            #pragma unroll
            for (int i = 0; i < 4; i++) {
                int idx = tid + (i << 8);
                ra[i] = *(const float4*)(Abase + (size_t)(idx >> 3) * DD + k0 + 32 + ((idx & 7) << 2));
            }
            #pragma unroll
            for (int i = 0; i < 2; i++) {
                int idx = tid + (i << 8);
                rb[i] = *(const float4*)(Wbase + (size_t)(idx >> 3) * DD + k0 + 32 + ((idx & 7) << 2));
            }
        }

        #pragma unroll
        for (int kt = 0; kt < 2; kt++) {
            unsigned ah[2][4];
            #pragma unroll
            for (int mt = 0; mt < 2; mt++) {
                int r = wm * 32 + mt * 16 + g;
                ah[mt][0] = Fh[ r      *GP + kt*8 + t    ];
                ah[mt][1] = Fh[(r + 8) *GP + kt*8 + t    ];
                ah[mt][2] = Fh[ r      *GP + kt*8 + t + 4];
                ah[mt][3] = Fh[(r + 8) *GP + kt*8 + t + 4];
            }
            #pragma unroll
            for (int nt = 0; nt < 4; nt++) {
                int r = wn * 32 + nt * 8 + g;
                unsigned bh0 = Bh[r*GP + kt*8 + t    ];
                unsigned bh1 = Bh[r*GP + kt*8 + t + 4];
                unsigned bl0 = Bl[r*GP + kt*8 + t    ];
                unsigned bl1 = Bl[r*GP + kt*8 + t + 4];
                #pragma unroll
                for (int mt = 0; mt < 2; mt++) {
                    mma16h(c[mt][nt], ah[mt], bl0, bl1);
                    mma16h(c[mt][nt], ah[mt], bh0, bh1);
                }
            }
        }
    }

    #pragma unroll
    for (int nt = 0; nt < 4; nt++) {
        int n = n0 + wn * 32 + nt * 8 + 2 * t;
        float b0 = bias[n], b1 = bias[n + 1];
        #pragma unroll
        for (int mt = 0; mt < 2; mt++) {
            int m = m0 + wm * 32 + mt * 16 + g;
            *(float2*)(C + (size_t)m * DD + n) =
                make_float2(c[mt][nt][0] + b0, c[mt][nt][1] + b1);
            *(float2*)(C + (size_t)(m + 8) * DD + n) =
                make_float2(c[mt][nt][2] + b0, c[mt][nt][3] + b1);
        }
    }
}

// ---------------------------------------------------------------------------
// Flash attention: QK^T 3xBF16 (pre-split operands), PV 2xFP16 (P rounded,
// V fp16 hi/lo). cp.async double-buffer, single sync/iter, in-register P,
// base-2 softmax, dist/mask LDG hoisted above the cp.async wait.
// ---------------------------------------------------------------------------
#define ATS 68
#define BUFW (2 * 64 * ATS)
#define SMEM_ATTN (2 * BUFW * (int)sizeof(unsigned))

__global__ __launch_bounds__(128, 3) void attn_bf16(
    const float* __restrict__ dist, const unsigned char* __restrict__ mask,
    const float* __restrict__ logwb)
{
    extern __shared__ unsigned smw[];

    const int tid  = threadIdx.x;
    const int lane = tid & 31;
    const int warp = tid >> 5;
    const int g = lane >> 2, t = lane & 3;

    const int bh = blockIdx.y;
    const int b  = bh >> 3, h = bh & 7;
    const int q0 = blockIdx.x << 6;

    const float wb = __expf(logwb[h]) * LOG2E;

    const unsigned* Ksrc0 = g_Khl + (size_t)bh * LL * 64;
    const unsigned* Vh0 = g_Vhl + (size_t)(bh*2    ) * 64 * 512;
    const unsigned* Vl0 = g_Vhl + (size_t)(bh*2 + 1) * 64 * 512;
    const float* db = dist + (size_t)b * LL * LL;
    const unsigned char* mb = mask + (size_t)b * LL * LL;

    const unsigned smem_u = smem_addr32(smw);

    auto prefetch = [&](int buf, int k0) {
        unsigned kb = smem_u + buf * BUFW * 4;
        unsigned vb = kb + 64 * ATS * 4;
        const unsigned* Ks = Ksrc0 + (size_t)k0 * 64;
        for (int i = tid; i < 1024; i += 128) {
            int r = i >> 4, cc = i & 15;
            cpa16(kb + r * 272 + cc * 16, Ks + (size_t)r * 64 + cc * 4);
        }
        const unsigned* vh = Vh0 + (k0 >> 1);
        const unsigned* vl = Vl0 + (k0 >> 1);
        for (int i = tid; i < 512; i += 128) {
            int r = i >> 3, cc = i & 7;
            cpa16(vb + r * 272 +       cc * 16, vh + (size_t)r * 512 + cc * 4);
            cpa16(vb + r * 272 + 128 + cc * 16, vl + (size_t)r * 512 + cc * 4);
        }
    };

    prefetch(0, 0);
    cpa_commit();

    // Q fragments: pre-scaled, pre-split in gmem
    unsigned qh[4][4], ql[4][4];
    {
        const unsigned* Qp = g_Qs + ((size_t)bh * LL + q0 + warp*16 + g) * 64;
        #pragma unroll
        for (int kt = 0; kt < 4; kt++) {
            int w = kt*8 + t;
            qh[kt][0] = Qp[w];            ql[kt][0] = Qp[32 + w];
            qh[kt][1] = Qp[512 + w];      ql[kt][1] = Qp[512 + 32 + w];
            qh[kt][2] = Qp[w + 4];        ql[kt][2] = Qp[32 + w + 4];
            qh[kt][3] = Qp[512 + w + 4];  ql[kt][3] = Qp[512 + 32 + w + 4];
        }
    }

    float o[8][4];
    #pragma unroll
    for (int nt = 0; nt < 8; nt++)
        #pragma unroll
        for (int k = 0; k < 4; k++) o[nt][k] = 0.f;
    float mrow[2] = {-1e30f, -1e30f};
    float lrow[2] = {0.f, 0.f};

    const int qr0 = q0 + warp * 16 + g;

    for (int it = 0; it < 16; it++) {
        const int k0 = it << 6;
        unsigned* Ks = smw + (it & 1) * BUFW;
        unsigned* Vs = Ks + 64 * ATS;

        // dist/mask loads first — pure gmem, overlap the cp.async wait below
        float2 d0a[8], d1a[8];
        unsigned short mk0a[8], mk1a[8];
        #pragma unroll
        for (int nt = 0; nt < 8; nt++) {
            int col = k0 + nt*8 + 2*t;
            d0a[nt] = *(const float2*)(db + (size_t)qr0 * LL + col);
            d1a[nt] = *(const float2*)(db + (size_t)(qr0 + 8) * LL + col);
            mk0a[nt] = *(const unsigned short*)(mb + (size_t)qr0 * LL + col);
            mk1a[nt] = *(const unsigned short*)(mb + (size_t)(qr0 + 8) * LL + col);
        }

        cpa_wait<0>();       // current tile landed (self)
        __syncthreads();     // all threads' copies landed; prev buffer free

        if (it + 1 < 16) {
            prefetch((it + 1) & 1, k0 + 64);
            cpa_commit();
        }

        // S = Q @ K^T (3xBF16, zero conversions)
        float s[8][4];
        #pragma unroll
        for (int nt = 0; nt < 8; nt++)
            #pragma unroll
            for (int k = 0; k < 4; k++) s[nt][k] = 0.f;

        #pragma unroll
        for (int kt = 0; kt < 4; kt++) {
            #pragma unroll
            for (int nt = 0; nt < 8; nt++) {
                int br = (nt*8 + g) * ATS + kt*8 + t;
                unsigned bh0 = Ks[br],      bh1 = Ks[br + 4];
                unsigned bl0 = Ks[br + 32], bl1 = Ks[br + 36];
                mma16(s[nt], ql[kt], bh0, bh1);
                mma16(s[nt], qh[kt], bl0, bl1);
                mma16(s[nt], qh[kt], bh0, bh1);
            }
        }

        // distance bias + mask (base-2 domain)
        #pragma unroll
        for (int nt = 0; nt < 8; nt++) {
            s[nt][0] -= d0a[nt].x * wb; if (mk0a[nt] & 0xffu) s[nt][0] = -1e9f;
            s[nt][1] -= d0a[nt].y * wb; if (mk0a[nt] >> 8)    s[nt][1] = -1e9f;
            s[nt][2] -= d1a[nt].x * wb; if (mk1a[nt] & 0xffu) s[nt][2] = -1e9f;
            s[nt][3] -= d1a[nt].y * wb; if (mk1a[nt] >> 8)    s[nt][3] = -1e9f;
        }

        // online softmax (base 2)
        #pragma unroll
        for (int i = 0; i < 2; i++) {
            float mx = -1e30f;
            #pragma unroll
            for (int nt = 0; nt < 8; nt++)
                mx = fmaxf(mx, fmaxf(s[nt][2*i], s[nt][2*i + 1]));
            mx = fmaxf(mx, __shfl_xor_sync(0xffffffffu, mx, 1));
            mx = fmaxf(mx, __shfl_xor_sync(0xffffffffu, mx, 2));
            float mnew  = fmaxf(mrow[i], mx);
            float alpha = ex2f(mrow[i] - mnew);
            float sum = 0.f;
            #pragma unroll
            for (int nt = 0; nt < 8; nt++) {
                s[nt][2*i]     = ex2f(s[nt][2*i]     - mnew);
                s[nt][2*i + 1] = ex2f(s[nt][2*i + 1] - mnew);
                sum += s[nt][2*i] + s[nt][2*i + 1];
            }
            sum += __shfl_xor_sync(0xffffffffu, sum, 1);
            sum += __shfl_xor_sync(0xffffffffu, sum, 2);
            lrow[i] = lrow[i] * alpha + sum;
            mrow[i] = mnew;
            #pragma unroll
            for (int nt = 0; nt < 8; nt++) {
                o[nt][2*i]     *= alpha;
                o[nt][2*i + 1] *= alpha;
            }
        }

        // O += P @ V (2xFP16: P rounded once, V hi+lo fully corrected)
        #pragma unroll
        for (int kt = 0; kt < 4; kt++) {
            unsigned pa[4];
            pa[0] = packf16(s[2*kt  ][0], s[2*kt  ][1]);
            pa[1] = packf16(s[2*kt  ][2], s[2*kt  ][3]);
            pa[2] = packf16(s[2*kt+1][0], s[2*kt+1][1]);
            pa[3] = packf16(s[2*kt+1][2], s[2*kt+1][3]);
            #pragma unroll
            for (int nt = 0; nt < 8; nt++) {
                int vr = (nt*8 + g) * ATS + kt*8 + t;
                unsigned vh0 = Vs[vr],      vh1 = Vs[vr + 4];
                unsigned vl0 = Vs[vr + 32], vl1 = Vs[vr + 36];
                mma16h(o[nt], pa, vl0, vl1);
                mma16h(o[nt], pa, vh0, vh1);
            }
        }
    }

    // normalize + write X (B,L,D)
    float inv0 = 1.0f / lrow[0], inv1 = 1.0f / lrow[1];
    float* X0 = g_X + ((size_t)b * LL + qr0)     * DD + h * DKK;
    float* X1 = g_X + ((size_t)b * LL + qr0 + 8) * DD + h * DKK;
    #pragma unroll
    for (int nt = 0; nt < 8; nt++) {
        *(float2*)&X0[nt*8 + 2*t] = make_float2(o[nt][0] * inv0, o[nt][1] * inv0);
        *(float2*)&X1[nt*8 + 2*t] = make_float2(o[nt][2] * inv1, o[nt][3] * inv1);
    }
}

// ---------------------------------------------------------------------------
extern "C" void kernel_launch(void* const* d_in, const int* in_sizes, int n_in,
                              void* d_out, int out_size)
{
    const float* query = (const float*)d_in[0];
    const float* key   = (const float*)d_in[1];
    const float* value = (const float*)d_in[2];
    const float* dist  = (const float*)d_in[3];
    const unsigned char* mask = (const unsigned char*)d_in[4];
    const float* Wq = (const float*)d_in[5];
    const float* bq = (const float*)d_in[6];
    const float* Wk = (const float*)d_in[7];
    const float* bk = (const float*)d_in[8];
    const float* Wv = (const float*)d_in[9];
    const float* bv = (const float*)d_in[10];
    const float* Wo = (const float*)d_in[11];
    const float* bo = (const float*)d_in[12];
    const float* logwb = (const float*)d_in[13];

    void *pX;
    cudaGetSymbolAddress(&pX, g_X);

    cudaFuncSetAttribute(attn_bf16,
                         cudaFuncAttributeMaxDynamicSharedMemorySize, SMEM_ATTN);

    // fused Q/K/V projections (V epilogue also does the transpose+fp16 split)
    dim3 gqkv(DD / 64, (BB * LL) / 128, 3);
    gemm_qkv<<<gqkv, 256>>>(query, Wq, bq, key, Wk, bk, value, Wv, bv);

    attn_bf16<<<dim3(LL / 64, BB * HH), 128, SMEM_ATTN>>>(dist, mask, logwb);

    dim3 go(DD / 64, (BB * LL) / 128);
    gemm_out<<<go, 256>>>((const float*)pX, Wo, bo, (float*)d_out);
}

// round 16
// speedup vs baseline: 1.3552x; 1.1554x over previous
#include <cuda_runtime.h>
#include <cuda_bf16.h>
#include <cstdint>
#include <math.h>

#define BB 8
#define LL 1024
#define DD 512
#define HH 8
#define DKK 64
#define LOG2E 1.4426950408889634f
#define QSC (0.125f * LOG2E)

// Scratch (__device__ globals; no runtime allocation)
__device__ float    g_X[BB*LL*DD];           // attention output (B,L,D)
__device__ unsigned g_Qs [BB*HH*LL*32];      // Q pre-scaled fp16x2 single: [bh][l][32 kpair]
__device__ unsigned g_Khl[BB*HH*LL*64];      // K fp16 split: [bh][l][32 hi | 32 lo]
__device__ unsigned g_Vhl[BB*HH*2*64*512];   // V fp16 split: [bh][plane][dk][512 kpair]

// ---------------------------------------------------------------------------
// helpers
// ---------------------------------------------------------------------------
__device__ __forceinline__ void mma16h(float* c, const unsigned* a, unsigned b0, unsigned b1) {
    asm volatile(
        "mma.sync.aligned.m16n8k16.row.col.f32.f16.f16.f32 "
        "{%0,%1,%2,%3}, {%4,%5,%6,%7}, {%8,%9}, {%0,%1,%2,%3};\n"
        : "+f"(c[0]), "+f"(c[1]), "+f"(c[2]), "+f"(c[3])
        : "r"(a[0]), "r"(a[1]), "r"(a[2]), "r"(a[3]), "r"(b0), "r"(b1));
}
__device__ __forceinline__ unsigned packf16(float lo_val, float hi_val) {
    unsigned d;
    asm("cvt.rn.f16x2.f32 %0, %1, %2;" : "=r"(d) : "f"(hi_val), "f"(lo_val));
    return d;
}
__device__ __forceinline__ void splitf162(float xe, float xo, unsigned& h, unsigned& l) {
    h = packf16(xe, xo);
    float fe, fo;
    asm("{ .reg .f16 a, b;\n\t"
        "mov.b32 {a, b}, %2;\n\t"
        "cvt.f32.f16 %0, a;\n\t"
        "cvt.f32.f16 %1, b; }"
        : "=f"(fe), "=f"(fo) : "r"(h));
    l = packf16(xe - fe, xo - fo);
}
__device__ __forceinline__ float ex2f(float x) {
    float r;
    asm("ex2.approx.f32 %0, %1;" : "=f"(r) : "f"(x));
    return r;
}
__device__ __forceinline__ void cpa16(unsigned dst, const void* src) {
    asm volatile("cp.async.ca.shared.global [%0], [%1], 16;\n" :: "r"(dst), "l"(src));
}
__device__ __forceinline__ void cpa_commit() {
    asm volatile("cp.async.commit_group;\n");
}
template <int N>
__device__ __forceinline__ void cpa_wait() {
    asm volatile("cp.async.wait_group %0;\n" :: "n"(N));
}
__device__ __forceinline__ unsigned smem_addr32(const void* p) {
    unsigned a;
    asm("{ .reg .u64 tmp; cvta.to.shared.u64 tmp, %1; cvt.u32.u64 %0, tmp; }"
        : "=r"(a) : "l"(p));
    return a;
}

// ---------------------------------------------------------------------------
// 2xFP16 GEMM core: A rounded to fp16, W split hi/lo fp16, fp32 accum.
// 128x64 C tile, BK=32, 256 threads (8 warps 4m x 2n), results in c[][][].
// smem: Fh[128][20] + Bh/Bl[64][20] words = 20,480 B.
// ---------------------------------------------------------------------------
#define GP 20

__device__ __forceinline__ void gemm2h_run(
    const float* __restrict__ A, const float* __restrict__ W,
    int m0, int n0, int tid,
    unsigned* Fh, unsigned* Bh, unsigned* Bl,
    float c[2][4][4])
{
    const int lane = tid & 31;
    const int warp = tid >> 5;
    const int g = lane >> 2, t = lane & 3;
    const int wm = warp & 3, wn = warp >> 2;

    #pragma unroll
    for (int mt = 0; mt < 2; mt++)
        #pragma unroll
        for (int nt = 0; nt < 4; nt++)
            #pragma unroll
            for (int k = 0; k < 4; k++) c[mt][nt][k] = 0.f;

    const float* Abase = A + (size_t)m0 * DD;
    const float* Wbase = W + (size_t)n0 * DD;

    float4 ra[4], rb[2];
    #pragma unroll
    for (int i = 0; i < 4; i++) {
        int idx = tid + (i << 8);
        ra[i] = *(const float4*)(Abase + (size_t)(idx >> 3) * DD + ((idx & 7) << 2));
    }
    #pragma unroll
    for (int i = 0; i < 2; i++) {
        int idx = tid + (i << 8);
        rb[i] = *(const float4*)(Wbase + (size_t)(idx >> 3) * DD + ((idx & 7) << 2));
    }

    for (int k0 = 0; k0 < DD; k0 += 32) {
        __syncthreads();
        #pragma unroll
        for (int i = 0; i < 4; i++) {
            int idx = tid + (i << 8);
            int row = idx >> 3, kp = (idx & 7) << 1;
            *(uint2*)&Fh[row*GP + kp] =
                make_uint2(packf16(ra[i].x, ra[i].y), packf16(ra[i].z, ra[i].w));
        }
        #pragma unroll
        for (int i = 0; i < 2; i++) {
            int idx = tid + (i << 8);
            int row = idx >> 3, kp = (idx & 7) << 1;
            unsigned h0, l0, h1, l1;
            splitf162(rb[i].x, rb[i].y, h0, l0);
            splitf162(rb[i].z, rb[i].w, h1, l1);
            *(uint2*)&Bh[row*GP + kp] = make_uint2(h0, h1);
            *(uint2*)&Bl[row*GP + kp] = make_uint2(l0, l1);
        }
        __syncthreads();

        if (k0 + 32 < DD) {
            #pragma unroll
            for (int i = 0; i < 4; i++) {
                int idx = tid + (i << 8);
                ra[i] = *(const float4*)(Abase + (size_t)(idx >> 3) * DD + k0 + 32 + ((idx & 7) << 2));
            }
            #pragma unroll
            for (int i = 0; i < 2; i++) {
                int idx = tid + (i << 8);
                rb[i] = *(const float4*)(Wbase + (size_t)(idx >> 3) * DD + k0 + 32 + ((idx & 7) << 2));
            }
        }

        #pragma unroll
        for (int kt = 0; kt < 2; kt++) {
            unsigned ah[2][4];
            #pragma unroll
            for (int mt = 0; mt < 2; mt++) {
                int r = wm * 32 + mt * 16 + g;
                ah[mt][0] = Fh[ r      *GP + kt*8 + t    ];
                ah[mt][1] = Fh[(r + 8) *GP + kt*8 + t    ];
                ah[mt][2] = Fh[ r      *GP + kt*8 + t + 4];
                ah[mt][3] = Fh[(r + 8) *GP + kt*8 + t + 4];
            }
            #pragma unroll
            for (int nt = 0; nt < 4; nt++) {
                int r = wn * 32 + nt * 8 + g;
                unsigned bh0 = Bh[r*GP + kt*8 + t    ];
                unsigned bh1 = Bh[r*GP + kt*8 + t + 4];
                unsigned bl0 = Bl[r*GP + kt*8 + t    ];
                unsigned bl1 = Bl[r*GP + kt*8 + t + 4];
                #pragma unroll
                for (int mt = 0; mt < 2; mt++) {
                    mma16h(c[mt][nt], ah[mt], bl0, bl1);
                    mma16h(c[mt][nt], ah[mt], bh0, bh1);
                }
            }
        }
    }
}

// ---------------------------------------------------------------------------
// Fused Q/K/V projection (2xFP16 core): z=0 -> Q (scaled, fp16 single -> g_Qs),
// z=1 -> K (fp16 split -> g_Khl), z=2 -> V (fp16 split + transpose -> g_Vhl).
// ---------------------------------------------------------------------------
__global__ __launch_bounds__(256) void gemm_qkv(
    const float* __restrict__ Aq, const float* __restrict__ Wq, const float* __restrict__ bq,
    const float* __restrict__ Ak, const float* __restrict__ Wk, const float* __restrict__ bk,
    const float* __restrict__ Av, const float* __restrict__ Wv, const float* __restrict__ bv)
{
    __shared__ unsigned Fh[128*GP], Bh[64*GP], Bl[64*GP];

    const int z = blockIdx.z;
    const float* A = (z == 0) ? Aq : (z == 1) ? Ak : Av;
    const float* W = (z == 0) ? Wq : (z == 1) ? Wk : Wv;
    const float* bias = (z == 0) ? bq : (z == 1) ? bk : bv;

    const int tid = threadIdx.x;
    const int lane = tid & 31;
    const int warp = tid >> 5;
    const int g = lane >> 2, t = lane & 3;
    const int wm = warp & 3, wn = warp >> 2;
    const int m0 = blockIdx.y << 7, n0 = blockIdx.x << 6;

    float c[2][4][4];
    gemm2h_run(A, W, m0, n0, tid, Fh, Bh, Bl, c);

    #pragma unroll
    for (int nt = 0; nt < 4; nt++) {
        int n = n0 + wn * 32 + nt * 8 + 2 * t;
        float b0 = bias[n], b1 = bias[n + 1];
        #pragma unroll
        for (int mt = 0; mt < 2; mt++) {
            int m = m0 + wm * 32 + mt * 16 + g;
            float x0 = c[mt][nt][0] + b0, x1 = c[mt][nt][1] + b1;
            float x2 = c[mt][nt][2] + b0, x3 = c[mt][nt][3] + b1;
            int b_ = m >> 10, l = m & 1023, hh = n >> 6;
            int dk = n & 63;
            if (z == 2) {
                // V: folded transpose+split via partner exchange (validated R15)
                float y0 = __shfl_xor_sync(0xffffffffu, x0, 4);
                float y1 = __shfl_xor_sync(0xffffffffu, x1, 4);
                float y2 = __shfl_xor_sync(0xffffffffu, x2, 4);
                float y3 = __shfl_xor_sync(0xffffffffu, x3, 4);
                int bhh = b_ * HH + hh;
                unsigned* vh = g_Vhl + (size_t)(bhh * 2    ) * 64 * 512;
                unsigned* vl = g_Vhl + (size_t)(bhh * 2 + 1) * 64 * 512;
                unsigned h, lw;
                if ((g & 1) == 0) {
                    int kp = l >> 1;
                    splitf162(x0, y0, h, lw);
                    vh[(size_t)dk * 512 + kp] = h;  vl[(size_t)dk * 512 + kp] = lw;
                    splitf162(x1, y1, h, lw);
                    vh[(size_t)(dk+1) * 512 + kp] = h;  vl[(size_t)(dk+1) * 512 + kp] = lw;
                } else {
                    int kp = (l + 7) >> 1;
                    splitf162(y2, x2, h, lw);
                    vh[(size_t)dk * 512 + kp] = h;  vl[(size_t)dk * 512 + kp] = lw;
                    splitf162(y3, x3, h, lw);
                    vh[(size_t)(dk+1) * 512 + kp] = h;  vl[(size_t)(dk+1) * 512 + kp] = lw;
                }
            } else if (z == 0) {
                // Q: scale, round to single fp16x2
                x0 *= QSC; x1 *= QSC; x2 *= QSC; x3 *= QSC;
                size_t bhl = ((size_t)b_ * HH + hh) * LL + l;
                unsigned* dst = g_Qs + bhl * 32 + (dk >> 1);
                dst[0]    = packf16(x0, x1);
                dst[8*32] = packf16(x2, x3);
            } else {
                // K: fp16 hi/lo split
                size_t bhl = ((size_t)b_ * HH + hh) * LL + l;
                unsigned* dst = g_Khl + bhl * 64 + (dk >> 1);
                unsigned h0, l0, h1, l1;
                splitf162(x0, x1, h0, l0);
                splitf162(x2, x3, h1, l1);
                dst[0]  = h0; dst[32] = l0;
                dst[8*64] = h1; dst[8*64 + 32] = l1;
            }
        }
    }
}

// ---------------------------------------------------------------------------
// Output projection (2xFP16 core, R15-proven)
// ---------------------------------------------------------------------------
__global__ __launch_bounds__(256) void gemm_out(
    const float* __restrict__ A, const float* __restrict__ W,
    const float* __restrict__ bias, float* __restrict__ C)
{
    __shared__ unsigned Fh[128*GP], Bh[64*GP], Bl[64*GP];

    const int tid = threadIdx.x;
    const int lane = tid & 31;
    const int warp = tid >> 5;
    const int g = lane >> 2, t = lane & 3;
    const int wm = warp & 3, wn = warp >> 2;
    const int m0 = blockIdx.y << 7, n0 = blockIdx.x << 6;

    float c[2][4][4];
    gemm2h_run(A, W, m0, n0, tid, Fh, Bh, Bl, c);

    #pragma unroll
    for (int nt = 0; nt < 4; nt++) {
        int n = n0 + wn * 32 + nt * 8 + 2 * t;
        float b0 = bias[n], b1 = bias[n + 1];
        #pragma unroll
        for (int mt = 0; mt < 2; mt++) {
            int m = m0 + wm * 32 + mt * 16 + g;
            *(float2*)(C + (size_t)m * DD + n) =
                make_float2(c[mt][nt][0] + b0, c[mt][nt][1] + b1);
            *(float2*)(C + (size_t)(m + 8) * DD + n) =
                make_float2(c[mt][nt][2] + b0, c[mt][nt][3] + b1);
        }
    }
}

// ---------------------------------------------------------------------------
// Flash attention: QK^T 2xFP16 (Q single fp16, K hi/lo), PV 2xFP16 (P rounded,
// V hi/lo). cp.async double-buffer, single sync/iter, in-register P,
// base-2 softmax, dist/mask LDG above the cp.async wait.
// smem: K tile [64 tok][68 w] + V tile [64 dk][68 w], x2 buffers = 69,632 B.
// ---------------------------------------------------------------------------
#define ATS 68
#define BUFW (2 * 64 * ATS)
#define SMEM_ATTN (2 * BUFW * (int)sizeof(unsigned))

__global__ __launch_bounds__(128, 3) void attn_f16(
    const float* __restrict__ dist, const unsigned char* __restrict__ mask,
    const float* __restrict__ logwb)
{
    extern __shared__ unsigned smw[];

    const int tid  = threadIdx.x;
    const int lane = tid & 31;
    const int warp = tid >> 5;
    const int g = lane >> 2, t = lane & 3;

    const int bh = blockIdx.y;
    const int b  = bh >> 3, h = bh & 7;
    const int q0 = blockIdx.x << 6;

    const float wb = __expf(logwb[h]) * LOG2E;

    const unsigned* Ksrc0 = g_Khl + (size_t)bh * LL * 64;
    const unsigned* Vh0 = g_Vhl + (size_t)(bh*2    ) * 64 * 512;
    const unsigned* Vl0 = g_Vhl + (size_t)(bh*2 + 1) * 64 * 512;
    const float* db = dist + (size_t)b * LL * LL;
    const unsigned char* mb = mask + (size_t)b * LL * LL;

    const unsigned smem_u = smem_addr32(smw);

    auto prefetch = [&](int buf, int k0) {
        unsigned kb = smem_u + buf * BUFW * 4;
        unsigned vb = kb + 64 * ATS * 4;
        const unsigned* Ks = Ksrc0 + (size_t)k0 * 64;
        for (int i = tid; i < 1024; i += 128) {
            int r = i >> 4, cc = i & 15;
            cpa16(kb + r * 272 + cc * 16, Ks + (size_t)r * 64 + cc * 4);
        }
        const unsigned* vh = Vh0 + (k0 >> 1);
        const unsigned* vl = Vl0 + (k0 >> 1);
        for (int i = tid; i < 512; i += 128) {
            int r = i >> 3, cc = i & 7;
            cpa16(vb + r * 272 +       cc * 16, vh + (size_t)r * 512 + cc * 4);
            cpa16(vb + r * 272 + 128 + cc * 16, vl + (size_t)r * 512 + cc * 4);
        }
    };

    prefetch(0, 0);
    cpa_commit();

    // Q fragments: pre-scaled single fp16, straight from gmem
    unsigned qa[4][4];
    {
        const unsigned* Qp = g_Qs + ((size_t)bh * LL + q0 + warp*16 + g) * 32;
        #pragma unroll
        for (int kt = 0; kt < 4; kt++) {
            int w = kt*8 + t;
            qa[kt][0] = Qp[w];
            qa[kt][1] = Qp[256 + w];
            qa[kt][2] = Qp[w + 4];
            qa[kt][3] = Qp[256 + w + 4];
        }
    }

    float o[8][4];
    #pragma unroll
    for (int nt = 0; nt < 8; nt++)
        #pragma unroll
        for (int k = 0; k < 4; k++) o[nt][k] = 0.f;
    float mrow[2] = {-1e30f, -1e30f};
    float lrow[2] = {0.f, 0.f};

    const int qr0 = q0 + warp * 16 + g;

    for (int it = 0; it < 16; it++) {
        const int k0 = it << 6;
        unsigned* Ks = smw + (it & 1) * BUFW;
        unsigned* Vs = Ks + 64 * ATS;

        // dist/mask loads first — overlap the cp.async wait
        float2 d0a[8], d1a[8];
        unsigned short mk0a[8], mk1a[8];
        #pragma unroll
        for (int nt = 0; nt < 8; nt++) {
            int col = k0 + nt*8 + 2*t;
            d0a[nt] = *(const float2*)(db + (size_t)qr0 * LL + col);
            d1a[nt] = *(const float2*)(db + (size_t)(qr0 + 8) * LL + col);
            mk0a[nt] = *(const unsigned short*)(mb + (size_t)qr0 * LL + col);
            mk1a[nt] = *(const unsigned short*)(mb + (size_t)(qr0 + 8) * LL + col);
        }

        cpa_wait<0>();
        __syncthreads();

        if (it + 1 < 16) {
            prefetch((it + 1) & 1, k0 + 64);
            cpa_commit();
        }

        // S = Q @ K^T (2xFP16: Q single, K hi+lo)
        float s[8][4];
        #pragma unroll
        for (int nt = 0; nt < 8; nt++)
            #pragma unroll
            for (int k = 0; k < 4; k++) s[nt][k] = 0.f;

        #pragma unroll
        for (int kt = 0; kt < 4; kt++) {
            #pragma unroll
            for (int nt = 0; nt < 8; nt++) {
                int br = (nt*8 + g) * ATS + kt*8 + t;
                unsigned bh0 = Ks[br],      bh1 = Ks[br + 4];
                unsigned bl0 = Ks[br + 32], bl1 = Ks[br + 36];
                mma16h(s[nt], qa[kt], bl0, bl1);
                mma16h(s[nt], qa[kt], bh0, bh1);
            }
        }

        // distance bias + mask (base-2 domain)
        #pragma unroll
        for (int nt = 0; nt < 8; nt++) {
            s[nt][0] -= d0a[nt].x * wb; if (mk0a[nt] & 0xffu) s[nt][0] = -1e9f;
            s[nt][1] -= d0a[nt].y * wb; if (mk0a[nt] >> 8)    s[nt][1] = -1e9f;
            s[nt][2] -= d1a[nt].x * wb; if (mk1a[nt] & 0xffu) s[nt][2] = -1e9f;
            s[nt][3] -= d1a[nt].y * wb; if (mk1a[nt] >> 8)    s[nt][3] = -1e9f;
        }

        // online softmax (base 2)
        #pragma unroll
        for (int i = 0; i < 2; i++) {
            float mx = -1e30f;
            #pragma unroll
            for (int nt = 0; nt < 8; nt++)
                mx = fmaxf(mx, fmaxf(s[nt][2*i], s[nt][2*i + 1]));
            mx = fmaxf(mx, __shfl_xor_sync(0xffffffffu, mx, 1));
            mx = fmaxf(mx, __shfl_xor_sync(0xffffffffu, mx, 2));
            float mnew  = fmaxf(mrow[i], mx);
            float alpha = ex2f(mrow[i] - mnew);
            float sum = 0.f;
            #pragma unroll
            for (int nt = 0; nt < 8; nt++) {
                s[nt][2*i]     = ex2f(s[nt][2*i]     - mnew);
                s[nt][2*i + 1] = ex2f(s[nt][2*i + 1] - mnew);
                sum += s[nt][2*i] + s[nt][2*i + 1];
            }
            sum += __shfl_xor_sync(0xffffffffu, sum, 1);
            sum += __shfl_xor_sync(0xffffffffu, sum, 2);
            lrow[i] = lrow[i] * alpha + sum;
            mrow[i] = mnew;
            #pragma unroll
            for (int nt = 0; nt < 8; nt++) {
                o[nt][2*i]     *= alpha;
                o[nt][2*i + 1] *= alpha;
            }
        }

        // O += P @ V (2xFP16: P rounded once, V hi+lo)
        #pragma unroll
        for (int kt = 0; kt < 4; kt++) {
            unsigned pa[4];
            pa[0] = packf16(s[2*kt  ][0], s[2*kt  ][1]);
            pa[1] = packf16(s[2*kt  ][2], s[2*kt  ][3]);
            pa[2] = packf16(s[2*kt+1][0], s[2*kt+1][1]);
            pa[3] = packf16(s[2*kt+1][2], s[2*kt+1][3]);
            #pragma unroll
            for (int nt = 0; nt < 8; nt++) {
                int vr = (nt*8 + g) * ATS + kt*8 + t;
                unsigned vh0 = Vs[vr],      vh1 = Vs[vr + 4];
                unsigned vl0 = Vs[vr + 32], vl1 = Vs[vr + 36];
                mma16h(o[nt], pa, vl0, vl1);
                mma16h(o[nt], pa, vh0, vh1);
            }
        }
    }

    // normalize + write X (B,L,D)
    float inv0 = 1.0f / lrow[0], inv1 = 1.0f / lrow[1];
    float* X0 = g_X + ((size_t)b * LL + qr0)     * DD + h * DKK;
    float* X1 = g_X + ((size_t)b * LL + qr0 + 8) * DD + h * DKK;
    #pragma unroll
    for (int nt = 0; nt < 8; nt++) {
        *(float2*)&X0[nt*8 + 2*t] = make_float2(o[nt][0] * inv0, o[nt][1] * inv0);
        *(float2*)&X1[nt*8 + 2*t] = make_float2(o[nt][2] * inv1, o[nt][3] * inv1);
    }
}

// ---------------------------------------------------------------------------
extern "C" void kernel_launch(void* const* d_in, const int* in_sizes, int n_in,
                              void* d_out, int out_size)
{
    const float* query = (const float*)d_in[0];
    const float* key   = (const float*)d_in[1];
    const float* value = (const float*)d_in[2];
    const float* dist  = (const float*)d_in[3];
    const unsigned char* mask = (const unsigned char*)d_in[4];
    const float* Wq = (const float*)d_in[5];
    const float* bq = (const float*)d_in[6];
    const float* Wk = (const float*)d_in[7];
    const float* bk = (const float*)d_in[8];
    const float* Wv = (const float*)d_in[9];
    const float* bv = (const float*)d_in[10];
    const float* Wo = (const float*)d_in[11];
    const float* bo = (const float*)d_in[12];
    const float* logwb = (const float*)d_in[13];

    void *pX;
    cudaGetSymbolAddress(&pX, g_X);

    cudaFuncSetAttribute(attn_f16,
                         cudaFuncAttributeMaxDynamicSharedMemorySize, SMEM_ATTN);

    // fused Q/K/V projections (2xFP16 core; V epilogue does transpose+split)
    dim3 gqkv(DD / 64, (BB * LL) / 128, 3);
    gemm_qkv<<<gqkv, 256>>>(query, Wq, bq, key, Wk, bk, value, Wv, bv);

    attn_f16<<<dim3(LL / 64, BB * HH), 128, SMEM_ATTN>>>(dist, mask, logwb);

    dim3 go(DD / 64, (BB * LL) / 128);
    gemm_out<<<go, 256>>>((const float*)pX, Wo, bo, (float*)d_out);
}

// round 17
// speedup vs baseline: 1.8106x; 1.3360x over previous
#include <cuda_runtime.h>
#include <cuda_bf16.h>
#include <cstdint>
#include <math.h>

#define BB 8
#define LL 1024
#define DD 512
#define HH 8
#define DKK 64
#define LOG2E 1.4426950408889634f
#define QSC (0.125f * LOG2E)

// Scratch (__device__ globals; no runtime allocation)
__device__ float    g_X[BB*LL*DD];          // attention output (B,L,D)
__device__ unsigned g_Qs[BB*HH*LL*32];      // Q pre-scaled fp16x2: [bh][l][32 kpair]
__device__ unsigned g_Ks[BB*HH*LL*32];      // K fp16x2: same layout
__device__ unsigned g_Vs[BB*HH*64*512];     // V fp16x2 transposed: [bh][dk][512 kpair]

// ---------------------------------------------------------------------------
// helpers
// ---------------------------------------------------------------------------
__device__ __forceinline__ void mma16h(float* c, const unsigned* a, unsigned b0, unsigned b1) {
    asm volatile(
        "mma.sync.aligned.m16n8k16.row.col.f32.f16.f16.f32 "
        "{%0,%1,%2,%3}, {%4,%5,%6,%7}, {%8,%9}, {%0,%1,%2,%3};\n"
        : "+f"(c[0]), "+f"(c[1]), "+f"(c[2]), "+f"(c[3])
        : "r"(a[0]), "r"(a[1]), "r"(a[2]), "r"(a[3]), "r"(b0), "r"(b1));
}
__device__ __forceinline__ unsigned packf16(float lo_val, float hi_val) {
    unsigned d;
    asm("cvt.rn.f16x2.f32 %0, %1, %2;" : "=r"(d) : "f"(hi_val), "f"(lo_val));
    return d;
}
__device__ __forceinline__ float ex2f(float x) {
    float r;
    asm("ex2.approx.f32 %0, %1;" : "=f"(r) : "f"(x));
    return r;
}
__device__ __forceinline__ void cpa16(unsigned dst, const void* src) {
    asm volatile("cp.async.ca.shared.global [%0], [%1], 16;\n" :: "r"(dst), "l"(src));
}
__device__ __forceinline__ void cpa_commit() {
    asm volatile("cp.async.commit_group;\n");
}
template <int N>
__device__ __forceinline__ void cpa_wait() {
    asm volatile("cp.async.wait_group %0;\n" :: "n"(N));
}
__device__ __forceinline__ unsigned smem_addr32(const void* p) {
    unsigned a;
    asm("{ .reg .u64 tmp; cvta.to.shared.u64 tmp, %1; cvt.u32.u64 %0, tmp; }"
        : "=r"(a) : "l"(p));
    return a;
}

// ---------------------------------------------------------------------------
// 1xFP16 GEMM core: A and W both rounded to fp16, fp32 accum.
// 128x64 C tile, BK=32, 256 threads (8 warps 4m x 2n).
// smem: Fh[128][20] + Bw[64][20] words = 15,360 B.
// ---------------------------------------------------------------------------
#define GP 20

__device__ __forceinline__ void gemm1h_run(
    const float* __restrict__ A, const float* __restrict__ W,
    int m0, int n0, int tid,
    unsigned* Fh, unsigned* Bw,
    float c[2][4][4])
{
    const int lane = tid & 31;
    const int warp = tid >> 5;
    const int g = lane >> 2, t = lane & 3;
    const int wm = warp & 3, wn = warp >> 2;

    #pragma unroll
    for (int mt = 0; mt < 2; mt++)
        #pragma unroll
        for (int nt = 0; nt < 4; nt++)
            #pragma unroll
            for (int k = 0; k < 4; k++) c[mt][nt][k] = 0.f;

    const float* Abase = A + (size_t)m0 * DD;
    const float* Wbase = W + (size_t)n0 * DD;

    float4 ra[4], rb[2];
    #pragma unroll
    for (int i = 0; i < 4; i++) {
        int idx = tid + (i << 8);
        ra[i] = *(const float4*)(Abase + (size_t)(idx >> 3) * DD + ((idx & 7) << 2));
    }
    #pragma unroll
    for (int i = 0; i < 2; i++) {
        int idx = tid + (i << 8);
        rb[i] = *(const float4*)(Wbase + (size_t)(idx >> 3) * DD + ((idx & 7) << 2));
    }

    for (int k0 = 0; k0 < DD; k0 += 32) {
        __syncthreads();
        #pragma unroll
        for (int i = 0; i < 4; i++) {
            int idx = tid + (i << 8);
            int row = idx >> 3, kp = (idx & 7) << 1;
            *(uint2*)&Fh[row*GP + kp] =
                make_uint2(packf16(ra[i].x, ra[i].y), packf16(ra[i].z, ra[i].w));
        }
        #pragma unroll
        for (int i = 0; i < 2; i++) {
            int idx = tid + (i << 8);
            int row = idx >> 3, kp = (idx & 7) << 1;
            *(uint2*)&Bw[row*GP + kp] =
                make_uint2(packf16(rb[i].x, rb[i].y), packf16(rb[i].z, rb[i].w));
        }
        __syncthreads();

        if (k0 + 32 < DD) {
            #pragma unroll
            for (int i = 0; i < 4; i++) {
                int idx = tid + (i << 8);
                ra[i] = *(const float4*)(Abase + (size_t)(idx >> 3) * DD + k0 + 32 + ((idx & 7) << 2));
            }
            #pragma unroll
            for (int i = 0; i < 2; i++) {
                int idx = tid + (i << 8);
                rb[i] = *(const float4*)(Wbase + (size_t)(idx >> 3) * DD + k0 + 32 + ((idx & 7) << 2));
            }
        }

        #pragma unroll
        for (int kt = 0; kt < 2; kt++) {
            unsigned ah[2][4];
            #pragma unroll
            for (int mt = 0; mt < 2; mt++) {
                int r = wm * 32 + mt * 16 + g;
                ah[mt][0] = Fh[ r      *GP + kt*8 + t    ];
                ah[mt][1] = Fh[(r + 8) *GP + kt*8 + t    ];
                ah[mt][2] = Fh[ r      *GP + kt*8 + t + 4];
                ah[mt][3] = Fh[(r + 8) *GP + kt*8 + t + 4];
            }
            #pragma unroll
            for (int nt = 0; nt < 4; nt++) {
                int r = wn * 32 + nt * 8 + g;
                unsigned b0 = Bw[r*GP + kt*8 + t    ];
                unsigned b1 = Bw[r*GP + kt*8 + t + 4];
                #pragma unroll
                for (int mt = 0; mt < 2; mt++)
                    mma16h(c[mt][nt], ah[mt], b0, b1);
            }
        }
    }
}

// ---------------------------------------------------------------------------
// Fused Q/K/V projection (1xFP16 core): z=0 -> Q (scaled fp16 -> g_Qs),
// z=1 -> K (fp16 -> g_Ks), z=2 -> V (fp16 + transpose -> g_Vs).
// ---------------------------------------------------------------------------
__global__ __launch_bounds__(256) void gemm_qkv(
    const float* __restrict__ Aq, const float* __restrict__ Wq, const float* __restrict__ bq,
    const float* __restrict__ Ak, const float* __restrict__ Wk, const float* __restrict__ bk,
    const float* __restrict__ Av, const float* __restrict__ Wv, const float* __restrict__ bv)
{
    __shared__ unsigned Fh[128*GP], Bw[64*GP];

    const int z = blockIdx.z;
    const float* A = (z == 0) ? Aq : (z == 1) ? Ak : Av;
    const float* W = (z == 0) ? Wq : (z == 1) ? Wk : Wv;
    const float* bias = (z == 0) ? bq : (z == 1) ? bk : bv;

    const int tid = threadIdx.x;
    const int lane = tid & 31;
    const int warp = tid >> 5;
    const int g = lane >> 2, t = lane & 3;
    const int wm = warp & 3, wn = warp >> 2;
    const int m0 = blockIdx.y << 7, n0 = blockIdx.x << 6;

    float c[2][4][4];
    gemm1h_run(A, W, m0, n0, tid, Fh, Bw, c);

    #pragma unroll
    for (int nt = 0; nt < 4; nt++) {
        int n = n0 + wn * 32 + nt * 8 + 2 * t;
        float b0 = bias[n], b1 = bias[n + 1];
        #pragma unroll
        for (int mt = 0; mt < 2; mt++) {
            int m = m0 + wm * 32 + mt * 16 + g;
            float x0 = c[mt][nt][0] + b0, x1 = c[mt][nt][1] + b1;
            float x2 = c[mt][nt][2] + b0, x3 = c[mt][nt][3] + b1;
            int b_ = m >> 10, l = m & 1023, hh = n >> 6;
            int dk = n & 63;
            if (z == 2) {
                // V: folded transpose via partner exchange (validated R15/R16)
                float y0 = __shfl_xor_sync(0xffffffffu, x0, 4);
                float y1 = __shfl_xor_sync(0xffffffffu, x1, 4);
                float y2 = __shfl_xor_sync(0xffffffffu, x2, 4);
                float y3 = __shfl_xor_sync(0xffffffffu, x3, 4);
                unsigned* vh = g_Vs + (size_t)(b_ * HH + hh) * 64 * 512;
                if ((g & 1) == 0) {
                    int kp = l >> 1;
                    vh[(size_t)dk * 512 + kp]       = packf16(x0, y0);
                    vh[(size_t)(dk + 1) * 512 + kp] = packf16(x1, y1);
                } else {
                    int kp = (l + 7) >> 1;
                    vh[(size_t)dk * 512 + kp]       = packf16(y2, x2);
                    vh[(size_t)(dk + 1) * 512 + kp] = packf16(y3, x3);
                }
            } else {
                if (z == 0) { x0 *= QSC; x1 *= QSC; x2 *= QSC; x3 *= QSC; }
                size_t bhl = ((size_t)b_ * HH + hh) * LL + l;
                unsigned* dst = (z == 0 ? g_Qs : g_Ks) + bhl * 32 + (dk >> 1);
                dst[0]    = packf16(x0, x1);
                dst[8*32] = packf16(x2, x3);
            }
        }
    }
}

// ---------------------------------------------------------------------------
// Output projection (1xFP16 core)
// ---------------------------------------------------------------------------
__global__ __launch_bounds__(256) void gemm_out(
    const float* __restrict__ A, const float* __restrict__ W,
    const float* __restrict__ bias, float* __restrict__ C)
{
    __shared__ unsigned Fh[128*GP], Bw[64*GP];

    const int tid = threadIdx.x;
    const int lane = tid & 31;
    const int warp = tid >> 5;
    const int g = lane >> 2, t = lane & 3;
    const int wm = warp & 3, wn = warp >> 2;
    const int m0 = blockIdx.y << 7, n0 = blockIdx.x << 6;

    float c[2][4][4];
    gemm1h_run(A, W, m0, n0, tid, Fh, Bw, c);

    #pragma unroll
    for (int nt = 0; nt < 4; nt++) {
        int n = n0 + wn * 32 + nt * 8 + 2 * t;
        float b0 = bias[n], b1 = bias[n + 1];
        #pragma unroll
        for (int mt = 0; mt < 2; mt++) {
            int m = m0 + wm * 32 + mt * 16 + g;
            *(float2*)(C + (size_t)m * DD + n) =
                make_float2(c[mt][nt][0] + b0, c[mt][nt][1] + b1);
            *(float2*)(C + (size_t)(m + 8) * DD + n) =
                make_float2(c[mt][nt][2] + b0, c[mt][nt][3] + b1);
        }
    }
}

// ---------------------------------------------------------------------------
// Flash attention, single-fp16 operands everywhere (fp32 accum):
// QK^T 1xFP16, PV 1xFP16. cp.async double-buffer, single sync/iter,
// in-register P, base-2 softmax, dist/mask LDG above the cp.async wait.
// smem: K tile [64 tok][36 w] + V tile [64 dk][36 w], x2 buffers = 36,864 B.
// Occupancy 4 blocks/SM (16 warps).
// ---------------------------------------------------------------------------
#define ATS 36
#define BUFW (2 * 64 * ATS)
#define SMEM_ATTN (2 * BUFW * (int)sizeof(unsigned))

__global__ __launch_bounds__(128, 4) void attn_f16(
    const float* __restrict__ dist, const unsigned char* __restrict__ mask,
    const float* __restrict__ logwb)
{
    extern __shared__ unsigned smw[];

    const int tid  = threadIdx.x;
    const int lane = tid & 31;
    const int warp = tid >> 5;
    const int g = lane >> 2, t = lane & 3;

    const int bh = blockIdx.y;
    const int b  = bh >> 3, h = bh & 7;
    const int q0 = blockIdx.x << 6;

    const float wb = __expf(logwb[h]) * LOG2E;

    const unsigned* Ksrc0 = g_Ks + (size_t)bh * LL * 32;
    const unsigned* Vsrc0 = g_Vs + (size_t)bh * 64 * 512;
    const float* db = dist + (size_t)b * LL * LL;
    const unsigned char* mb = mask + (size_t)b * LL * LL;

    const unsigned smem_u = smem_addr32(smw);

    auto prefetch = [&](int buf, int k0) {
        unsigned kb = smem_u + buf * BUFW * 4;
        unsigned vb = kb + 64 * ATS * 4;
        const unsigned* Ksp = Ksrc0 + (size_t)k0 * 32;
        for (int i = tid; i < 512; i += 128) {       // K: 64 rows x 8 chunks
            int r = i >> 3, cc = i & 7;
            cpa16(kb + r * 144 + cc * 16, Ksp + (size_t)r * 32 + cc * 4);
        }
        const unsigned* Vsp = Vsrc0 + (k0 >> 1);
        for (int i = tid; i < 512; i += 128) {       // V: 64 dk x 8 chunks
            int r = i >> 3, cc = i & 7;
            cpa16(vb + r * 144 + cc * 16, Vsp + (size_t)r * 512 + cc * 4);
        }
    };

    prefetch(0, 0);
    cpa_commit();

    // Q fragments: pre-scaled single fp16, straight from gmem
    unsigned qa[4][4];
    {
        const unsigned* Qp = g_Qs + ((size_t)bh * LL + q0 + warp*16 + g) * 32;
        #pragma unroll
        for (int kt = 0; kt < 4; kt++) {
            int w = kt*8 + t;
            qa[kt][0] = Qp[w];
            qa[kt][1] = Qp[256 + w];
            qa[kt][2] = Qp[w + 4];
            qa[kt][3] = Qp[256 + w + 4];
        }
    }

    float o[8][4];
    #pragma unroll
    for (int nt = 0; nt < 8; nt++)
        #pragma unroll
        for (int k = 0; k < 4; k++) o[nt][k] = 0.f;
    float mrow[2] = {-1e30f, -1e30f};
    float lrow[2] = {0.f, 0.f};

    const int qr0 = q0 + warp * 16 + g;

    for (int it = 0; it < 16; it++) {
        const int k0 = it << 6;
        unsigned* Ks = smw + (it & 1) * BUFW;
        unsigned* Vs = Ks + 64 * ATS;

        // dist/mask loads — overlap the cp.async wait
        float2 d0a[8], d1a[8];
        unsigned short mk0a[8], mk1a[8];
        #pragma unroll
        for (int nt = 0; nt < 8; nt++) {
            int col = k0 + nt*8 + 2*t;
            d0a[nt] = *(const float2*)(db + (size_t)qr0 * LL + col);
            d1a[nt] = *(const float2*)(db + (size_t)(qr0 + 8) * LL + col);
            mk0a[nt] = *(const unsigned short*)(mb + (size_t)qr0 * LL + col);
            mk1a[nt] = *(const unsigned short*)(mb + (size_t)(qr0 + 8) * LL + col);
        }

        cpa_wait<0>();
        __syncthreads();

        if (it + 1 < 16) {
            prefetch((it + 1) & 1, k0 + 64);
            cpa_commit();
        }

        // S = Q @ K^T (1xFP16)
        float s[8][4];
        #pragma unroll
        for (int nt = 0; nt < 8; nt++)
            #pragma unroll
            for (int k = 0; k < 4; k++) s[nt][k] = 0.f;

        #pragma unroll
        for (int kt = 0; kt < 4; kt++) {
            #pragma unroll
            for (int nt = 0; nt < 8; nt++) {
                int br = (nt*8 + g) * ATS + kt*8 + t;
                mma16h(s[nt], qa[kt], Ks[br], Ks[br + 4]);
            }
        }

        // distance bias + mask (base-2 domain)
        #pragma unroll
        for (int nt = 0; nt < 8; nt++) {
            s[nt][0] -= d0a[nt].x * wb; if (mk0a[nt] & 0xffu) s[nt][0] = -1e9f;
            s[nt][1] -= d0a[nt].y * wb; if (mk0a[nt] >> 8)    s[nt][1] = -1e9f;
            s[nt][2] -= d1a[nt].x * wb; if (mk1a[nt] & 0xffu) s[nt][2] = -1e9f;
            s[nt][3] -= d1a[nt].y * wb; if (mk1a[nt] >> 8)    s[nt][3] = -1e9f;
        }

        // online softmax (base 2)
        #pragma unroll
        for (int i = 0; i < 2; i++) {
            float mx = -1e30f;
            #pragma unroll
            for (int nt = 0; nt < 8; nt++)
                mx = fmaxf(mx, fmaxf(s[nt][2*i], s[nt][2*i + 1]));
            mx = fmaxf(mx, __shfl_xor_sync(0xffffffffu, mx, 1));
            mx = fmaxf(mx, __shfl_xor_sync(0xffffffffu, mx, 2));
            float mnew  = fmaxf(mrow[i], mx);
            float alpha = ex2f(mrow[i] - mnew);
            float sum = 0.f;
            #pragma unroll
            for (int nt = 0; nt < 8; nt++) {
                s[nt][2*i]     = ex2f(s[nt][2*i]     - mnew);
                s[nt][2*i + 1] = ex2f(s[nt][2*i + 1] - mnew);
                sum += s[nt][2*i] + s[nt][2*i + 1];
            }
            sum += __shfl_xor_sync(0xffffffffu, sum, 1);
            sum += __shfl_xor_sync(0xffffffffu, sum, 2);
            lrow[i] = lrow[i] * alpha + sum;
            mrow[i] = mnew;
            #pragma unroll
            for (int nt = 0; nt < 8; nt++) {
                o[nt][2*i]     *= alpha;
                o[nt][2*i + 1] *= alpha;
            }
        }

        // O += P @ V (1xFP16: P rounded once, V single)
        #pragma unroll
        for (int kt = 0; kt < 4; kt++) {
            unsigned pa[4];
            pa[0] = packf16(s[2*kt  ][0], s[2*kt  ][1]);
            pa[1] = packf16(s[2*kt  ][2], s[2*kt  ][3]);
            pa[2] = packf16(s[2*kt+1][0], s[2*kt+1][1]);
            pa[3] = packf16(s[2*kt+1][2], s[2*kt+1][3]);
            #pragma unroll
            for (int nt = 0; nt < 8; nt++) {
                int vr = (nt*8 + g) * ATS + kt*8 + t;
                mma16h(o[nt], pa, Vs[vr], Vs[vr + 4]);
            }
        }
    }

    // normalize + write X (B,L,D)
    float inv0 = 1.0f / lrow[0], inv1 = 1.0f / lrow[1];
    float* X0 = g_X + ((size_t)b * LL + qr0)     * DD + h * DKK;
    float* X1 = g_X + ((size_t)b * LL + qr0 + 8) * DD + h * DKK;
    #pragma unroll
    for (int nt = 0; nt < 8; nt++) {
        *(float2*)&X0[nt*8 + 2*t] = make_float2(o[nt][0] * inv0, o[nt][1] * inv0);
        *(float2*)&X1[nt*8 + 2*t] = make_float2(o[nt][2] * inv1, o[nt][3] * inv1);
    }
}

// ---------------------------------------------------------------------------
extern "C" void kernel_launch(void* const* d_in, const int* in_sizes, int n_in,
                              void* d_out, int out_size)
{
    const float* query = (const float*)d_in[0];
    const float* key   = (const float*)d_in[1];
    const float* value = (const float*)d_in[2];
    const float* dist  = (const float*)d_in[3];
    const unsigned char* mask = (const unsigned char*)d_in[4];
    const float* Wq = (const float*)d_in[5];
    const float* bq = (const float*)d_in[6];
    const float* Wk = (const float*)d_in[7];
    const float* bk = (const float*)d_in[8];
    const float* Wv = (const float*)d_in[9];
    const float* bv = (const float*)d_in[10];
    const float* Wo = (const float*)d_in[11];
    const float* bo = (const float*)d_in[12];
    const float* logwb = (const float*)d_in[13];

    void *pX;
    cudaGetSymbolAddress(&pX, g_X);

    cudaFuncSetAttribute(attn_f16,
                         cudaFuncAttributeMaxDynamicSharedMemorySize, SMEM_ATTN);

    // fused Q/K/V projections (1xFP16 core; V epilogue does transpose)
    dim3 gqkv(DD / 64, (BB * LL) / 128, 3);
    gemm_qkv<<<gqkv, 256>>>(query, Wq, bq, key, Wk, bk, value, Wv, bv);

    attn_f16<<<dim3(LL / 64, BB * HH), 128, SMEM_ATTN>>>(dist, mask, logwb);

    dim3 go(DD / 64, (BB * LL) / 128);
    gemm_out<<<go, 256>>>((const float*)pX, Wo, bo, (float*)d_out);
}